// round 1
// baseline (speedup 1.0000x reference)
#include <cuda_runtime.h>
#include <math.h>

#define BATCH 4
#define SEQ   1024
#define DIMC  768
#define NH    12
#define HD    64
#define RK    8
#define MTOT  (BATCH*SEQ)     /* 4096 */
#define BH    (BATCH*NH)      /* 48   */

// ---------------- scratch (device globals; no allocation allowed) ----------
__device__ __align__(16) float g_q  [MTOT*DIMC];
__device__ __align__(16) float g_k  [MTOT*DIMC];
__device__ __align__(16) float g_v  [MTOT*DIMC];
__device__ __align__(16) float g_ctx[MTOT*DIMC];
__device__ __align__(16) float g_lq [BH*SEQ*RK];
__device__ __align__(16) float g_lk [BH*SEQ*RK];
__device__ __align__(16) float g_lq2[BH*SEQ];
__device__ __align__(16) float g_lk2[BH*SEQ];
__device__ float g_klpart[256];

// ---------------- fast approx helpers --------------------------------------
__device__ __forceinline__ float ex2a(float x) {
    float y; asm("ex2.approx.f32 %0, %1;" : "=f"(y) : "f"(x)); return y;
}
__device__ __forceinline__ float rsqa(float x) {
    float y; asm("rsqrt.approx.f32 %0, %1;" : "=f"(y) : "f"(x)); return y;
}

// ---------------- SGEMM: C[M,Ncols] = A[M,K] * B[Ncols,K]^T (+bias) --------
// Both A and B are K-major row-major ("NT" gemm). All dims multiples of 128/16.
__global__ __launch_bounds__(256, 2)
void sgemm_nt(const float* __restrict__ A, const float* __restrict__ Bm,
              float* __restrict__ C, const float* __restrict__ bias,
              int M, int Ncols, int K)
{
    __shared__ float As[16][128];
    __shared__ float Bs[16][128];
    const int m0 = blockIdx.y * 128;
    const int n0 = blockIdx.x * 128;
    const int tid = threadIdx.x;
    const int tx = tid & 15;
    const int ty = tid >> 4;

    float acc[8][8];
#pragma unroll
    for (int i = 0; i < 8; i++)
#pragma unroll
        for (int j = 0; j < 8; j++) acc[i][j] = 0.f;

    for (int kt = 0; kt < K; kt += 16) {
#pragma unroll
        for (int u = 0; u < 2; ++u) {
            int f   = tid + u * 256;      // 0..511 float4 slots
            int row = f >> 2;
            int kc  = (f & 3) << 2;
            float4 va = *reinterpret_cast<const float4*>(A + (size_t)(m0 + row) * K + kt + kc);
            As[kc + 0][row] = va.x; As[kc + 1][row] = va.y;
            As[kc + 2][row] = va.z; As[kc + 3][row] = va.w;
            float4 vb = *reinterpret_cast<const float4*>(Bm + (size_t)(n0 + row) * K + kt + kc);
            Bs[kc + 0][row] = vb.x; Bs[kc + 1][row] = vb.y;
            Bs[kc + 2][row] = vb.z; Bs[kc + 3][row] = vb.w;
        }
        __syncthreads();
#pragma unroll
        for (int k = 0; k < 16; k++) {
            float a[8], b[8];
            *(float4*)&a[0] = *(const float4*)&As[k][ty * 8];
            *(float4*)&a[4] = *(const float4*)&As[k][ty * 8 + 4];
            *(float4*)&b[0] = *(const float4*)&Bs[k][tx * 8];
            *(float4*)&b[4] = *(const float4*)&Bs[k][tx * 8 + 4];
#pragma unroll
            for (int i = 0; i < 8; i++)
#pragma unroll
                for (int j = 0; j < 8; j++)
                    acc[i][j] = fmaf(a[i], b[j], acc[i][j]);
        }
        __syncthreads();
    }

#pragma unroll
    for (int i = 0; i < 8; i++) {
        int row = m0 + ty * 8 + i;
#pragma unroll
        for (int j = 0; j < 8; j += 4) {
            int col = n0 + tx * 8 + j;
            float4 r;
            r.x = acc[i][j + 0]; r.y = acc[i][j + 1];
            r.z = acc[i][j + 2]; r.w = acc[i][j + 3];
            if (bias) {
                r.x += bias[col + 0]; r.y += bias[col + 1];
                r.z += bias[col + 2]; r.w += bias[col + 3];
            }
            *reinterpret_cast<float4*>(C + (size_t)row * Ncols + col) = r;
        }
    }
}

// ---------------- SPD log-projection: larr[(bh,n),r] = log(softplus(q.w+b)+1e-6+1e-8)
__global__ __launch_bounds__(256)
void lproj_kernel(const float* __restrict__ src, const float* __restrict__ w,
                  const float* __restrict__ bias, float* __restrict__ larr,
                  float* __restrict__ l2arr)
{
    int g = blockIdx.x * blockDim.x + threadIdx.x;   // 0 .. BH*SEQ*RK
    int t = g >> 3;            // token id over (bh, n)
    int r = g & 7;
    int bh = t >> 10;
    int n  = t & 1023;
    int b  = bh / NH;
    int h  = bh - b * NH;
    const float* row = src + (size_t)(b * SEQ + n) * DIMC + h * HD;
    const float* wr  = w + r * HD;
    float z = bias[r];
#pragma unroll
    for (int d = 0; d < HD; d++) z = fmaf(row[d], wr[d], z);
    float sp = (z > 20.f) ? z : log1pf(expf(z));
    float lv = logf(sp + 1e-6f + 1e-8f);
    larr[(size_t)t * RK + r] = lv;
    float s = lv * lv;
    s += __shfl_xor_sync(0xffffffffu, s, 1);
    s += __shfl_xor_sync(0xffffffffu, s, 2);
    s += __shfl_xor_sync(0xffffffffu, s, 4);
    if (r == 0) l2arr[t] = s;
}

// ---------------- fused geodesic attention (flash-style, no max tracking) --
// scores in [-~0.07, 0] -> exp is always safe without running-max rescale.
__global__ __launch_bounds__(128)
void attn_kernel()
{
    __shared__ float4 s_v4 [64][16];
    __shared__ float4 s_lk4[64][2];
    __shared__ float  s_lk2[64];

    const int qb  = blockIdx.x;        // 0..7  (query tile of 128)
    const int bh  = blockIdx.y;        // 0..47
    const int b   = bh / NH;
    const int h   = bh - b * NH;
    const int tid = threadIdx.x;       // one thread per query
    const int n   = qb * 128 + tid;

    const float* Vp  = g_v  + (size_t)(b * SEQ) * DIMC + h * HD;
    const float* Lk  = g_lk + (size_t)bh * SEQ * RK;
    const float* Lk2 = g_lk2 + (size_t)bh * SEQ;

    const float* lqp = g_lq + (size_t)bh * SEQ * RK + (size_t)n * RK;
    float4 lqa = *(const float4*)(lqp);
    float4 lqb = *(const float4*)(lqp + 4);
    float lq2 = lqa.x * lqa.x + lqa.y * lqa.y + lqa.z * lqa.z + lqa.w * lqa.w
              + lqb.x * lqb.x + lqb.y * lqb.y + lqb.z * lqb.z + lqb.w * lqb.w;

    float4 o4[16];
#pragma unroll
    for (int i = 0; i < 16; i++) o4[i] = make_float4(0.f, 0.f, 0.f, 0.f);
    float lsum = 0.f;
    const float CEXP = -0.125f * 1.4426950408889634f;  // -SCALE * log2(e)

    for (int kt = 0; kt < 16; ++kt) {
        int key0 = kt * 64;
        {
            int key = tid >> 1, rp = tid & 1;
            s_lk4[key][rp] = *(const float4*)(Lk + (size_t)(key0 + key) * RK + rp * 4);
            if (tid < 64) s_lk2[tid] = Lk2[key0 + tid];
        }
#pragma unroll
        for (int u = 0; u < 8; u++) {
            int f = tid + u * 128;        // 0..1023 float4 slots of V tile
            int key = f >> 4, d4 = f & 15;
            s_v4[key][d4] = *(const float4*)(Vp + (size_t)(key0 + key) * DIMC + d4 * 4);
        }
        __syncthreads();

#pragma unroll 2
        for (int j = 0; j < 64; j++) {
            float4 k0 = s_lk4[j][0];
            float4 k1 = s_lk4[j][1];
            float dot = lqa.x * k0.x;
            dot = fmaf(lqa.y, k0.y, dot);
            dot = fmaf(lqa.z, k0.z, dot);
            dot = fmaf(lqa.w, k0.w, dot);
            dot = fmaf(lqb.x, k1.x, dot);
            dot = fmaf(lqb.y, k1.y, dot);
            dot = fmaf(lqb.z, k1.z, dot);
            dot = fmaf(lqb.w, k1.w, dot);
            float d2 = fmaxf(fmaf(-2.f, dot, lq2 + s_lk2[j]), 1e-12f);
            float dist = d2 * rsqa(d2);                 // sqrt(d2)
            float p = ex2a(CEXP * dist);                // exp(-SCALE*dist)
            lsum += p;
            const float4* vr = s_v4[j];
#pragma unroll
            for (int t2 = 0; t2 < 16; t2++) {
                float4 vv = vr[t2];
                o4[t2].x = fmaf(p, vv.x, o4[t2].x);
                o4[t2].y = fmaf(p, vv.y, o4[t2].y);
                o4[t2].z = fmaf(p, vv.z, o4[t2].z);
                o4[t2].w = fmaf(p, vv.w, o4[t2].w);
            }
        }
        __syncthreads();
    }

    float inv = 1.0f / lsum;
    float* Op = g_ctx + (size_t)(b * SEQ + n) * DIMC + h * HD;
#pragma unroll
    for (int t2 = 0; t2 < 16; t2++) {
        float4 r = o4[t2];
        r.x *= inv; r.y *= inv; r.z *= inv; r.w *= inv;
        *(float4*)(Op + t2 * 4) = r;
    }
}

// ---------------- KL term (deterministic two-stage reduction) --------------
__global__ __launch_bounds__(256)
void kl_partial(const float* __restrict__ m0, const float* __restrict__ l0,
                const float* __restrict__ m1, const float* __restrict__ l1,
                const float* __restrict__ m2, const float* __restrict__ l2,
                const float* __restrict__ m3, const float* __restrict__ l3)
{
    const int PER = DIMC * DIMC;       // 589824
    const int TOT = 4 * PER;
    float s = 0.f;
    for (int idx = blockIdx.x * blockDim.x + threadIdx.x; idx < TOT;
         idx += gridDim.x * blockDim.x) {
        int p   = idx / PER;
        int off = idx - p * PER;
        const float* mp = (p == 0) ? m0 : (p == 1) ? m1 : (p == 2) ? m2 : m3;
        const float* lp = (p == 0) ? l0 : (p == 1) ? l1 : (p == 2) ? l2 : l3;
        float mu = mp[off], ls = lp[off];
        s += 0.5f * (expf(2.f * ls) + mu * mu - 1.f - 2.f * ls);
    }
    __shared__ float red[256];
    red[threadIdx.x] = s;
    __syncthreads();
    for (int w = 128; w > 0; w >>= 1) {
        if (threadIdx.x < w) red[threadIdx.x] += red[threadIdx.x + w];
        __syncthreads();
    }
    if (threadIdx.x == 0) g_klpart[blockIdx.x] = red[0];
}

__global__ void kl_final(float* __restrict__ dst)
{
    __shared__ float red[256];
    red[threadIdx.x] = g_klpart[threadIdx.x];
    __syncthreads();
    for (int w = 128; w > 0; w >>= 1) {
        if (threadIdx.x < w) red[threadIdx.x] += red[threadIdx.x + w];
        __syncthreads();
    }
    if (threadIdx.x == 0) *dst = red[0];
}

// ---------------- launcher -------------------------------------------------
extern "C" void kernel_launch(void* const* d_in, const int* in_sizes, int n_in,
                              void* d_out, int out_size)
{
    const float* x     = (const float*)d_in[0];
    const float* wq_mu = (const float*)d_in[1];
    const float* wq_ls = (const float*)d_in[2];
    const float* wk_mu = (const float*)d_in[3];
    const float* wk_ls = (const float*)d_in[4];
    const float* wv_mu = (const float*)d_in[5];
    const float* wv_ls = (const float*)d_in[6];
    const float* wo_mu = (const float*)d_in[7];
    const float* wo_ls = (const float*)d_in[8];
    const float* wo_b  = (const float*)d_in[9];
    const float* sq_w  = (const float*)d_in[10];
    const float* sq_b  = (const float*)d_in[11];
    const float* sk_w  = (const float*)d_in[12];
    const float* sk_b  = (const float*)d_in[13];
    float* out = (float*)d_out;

    float *q_d, *k_d, *v_d, *ctx_d, *lq_d, *lk_d, *lq2_d, *lk2_d;
    cudaGetSymbolAddress((void**)&q_d,   g_q);
    cudaGetSymbolAddress((void**)&k_d,   g_k);
    cudaGetSymbolAddress((void**)&v_d,   g_v);
    cudaGetSymbolAddress((void**)&ctx_d, g_ctx);
    cudaGetSymbolAddress((void**)&lq_d,  g_lq);
    cudaGetSymbolAddress((void**)&lk_d,  g_lk);
    cudaGetSymbolAddress((void**)&lq2_d, g_lq2);
    cudaGetSymbolAddress((void**)&lk2_d, g_lk2);

    dim3 gqkv(DIMC / 128, MTOT / 128);   // (6, 32)
    sgemm_nt<<<gqkv, 256>>>(x, wq_mu, q_d, nullptr, MTOT, DIMC, DIMC);
    sgemm_nt<<<gqkv, 256>>>(x, wk_mu, k_d, nullptr, MTOT, DIMC, DIMC);
    sgemm_nt<<<gqkv, 256>>>(x, wv_mu, v_d, nullptr, MTOT, DIMC, DIMC);

    int lpgrid = (BH * SEQ * RK) / 256;  // 1536
    lproj_kernel<<<lpgrid, 256>>>(q_d, sq_w, sq_b, lq_d, lq2_d);
    lproj_kernel<<<lpgrid, 256>>>(k_d, sk_w, sk_b, lk_d, lk2_d);

    attn_kernel<<<dim3(SEQ / 128, BH), 128>>>();

    sgemm_nt<<<gqkv, 256>>>(ctx_d, wo_mu, out, wo_b, MTOT, DIMC, DIMC);

    kl_partial<<<256, 256>>>(wq_mu, wq_ls, wk_mu, wk_ls,
                             wv_mu, wv_ls, wo_mu, wo_ls);
    if (out_size > MTOT * DIMC) {
        kl_final<<<1, 256>>>(out + (size_t)out_size - 1);
    }
}

// round 4
// speedup vs baseline: 1.8482x; 1.8482x over previous
#include <cuda_runtime.h>
#include <cuda_bf16.h>
#include <cstdint>
#include <math.h>

#define BATCH 4
#define SEQ   1024
#define DIMC  768
#define NH    12
#define HD    64
#define RK    8
#define MTOT  (BATCH*SEQ)     /* 4096 */
#define BH    (BATCH*NH)      /* 48   */
#define KDIM  768

// ---------------- scratch (device globals; no allocation allowed) ----------
__device__ __align__(16) float g_qkv[3*MTOT*DIMC];     // q,k,v planes
__device__ __align__(16) float g_lq [BH*SEQ*RK];
__device__ __align__(16) float g_lk [BH*SEQ*RK];
__device__ __align__(16) float g_lq2[BH*SEQ];
__device__ __align__(16) float g_lk2[BH*SEQ];
__device__ float g_klpart[256];
// bf16 hi/lo planes
__device__ __align__(16) __nv_bfloat16 g_xh [MTOT*DIMC];
__device__ __align__(16) __nv_bfloat16 g_xl [MTOT*DIMC];
__device__ __align__(16) __nv_bfloat16 g_wh [3*DIMC*DIMC];
__device__ __align__(16) __nv_bfloat16 g_wl [3*DIMC*DIMC];
__device__ __align__(16) __nv_bfloat16 g_woh[DIMC*DIMC];
__device__ __align__(16) __nv_bfloat16 g_wol[DIMC*DIMC];
__device__ __align__(16) __nv_bfloat16 g_ch [MTOT*DIMC];
__device__ __align__(16) __nv_bfloat16 g_cl [MTOT*DIMC];

// ---------------- fast approx helpers --------------------------------------
__device__ __forceinline__ float ex2a(float x) {
    float y; asm("ex2.approx.f32 %0, %1;" : "=f"(y) : "f"(x)); return y;
}
__device__ __forceinline__ float rsqa(float x) {
    float y; asm("rsqrt.approx.f32 %0, %1;" : "=f"(y) : "f"(x)); return y;
}

// ---------------- portable tensor-core primitives (sm_80+) ------------------
__device__ __forceinline__ uint32_t smem_u32(const void* p) {
    uint32_t a;
    asm("{ .reg .u64 t; cvta.to.shared.u64 t, %1; cvt.u32.u64 %0, t; }"
        : "=r"(a) : "l"(p));
    return a;
}
__device__ __forceinline__ void cpasync16(uint32_t dst, const void* src) {
    asm volatile("cp.async.cg.shared.global [%0], [%1], 16;"
                 :: "r"(dst), "l"(src));
}
#define CP_COMMIT() asm volatile("cp.async.commit_group;" ::: "memory")
#define CP_WAIT(n)  asm volatile("cp.async.wait_group %0;" :: "n"(n) : "memory")

__device__ __forceinline__ void ldsm4(uint32_t* r, uint32_t addr) {
    asm volatile("ldmatrix.sync.aligned.m8n8.x4.shared.b16 {%0,%1,%2,%3}, [%4];"
        : "=r"(r[0]), "=r"(r[1]), "=r"(r[2]), "=r"(r[3]) : "r"(addr));
}
__device__ __forceinline__ void mma16816(float* c, const uint32_t* a,
                                         const uint32_t* b) {
    asm volatile(
        "mma.sync.aligned.m16n8k16.row.col.f32.bf16.bf16.f32 "
        "{%0,%1,%2,%3}, {%4,%5,%6,%7}, {%8,%9}, {%0,%1,%2,%3};"
        : "+f"(c[0]), "+f"(c[1]), "+f"(c[2]), "+f"(c[3])
        : "r"(a[0]), "r"(a[1]), "r"(a[2]), "r"(a[3]), "r"(b[0]), "r"(b[1]));
}

// ---------------- split fp32 -> bf16 hi/lo ----------------------------------
__global__ __launch_bounds__(256)
void split_kernel(const float* __restrict__ src, __nv_bfloat16* __restrict__ hi,
                  __nv_bfloat16* __restrict__ lo, int n4)
{
    int i = blockIdx.x * blockDim.x + threadIdx.x;
    if (i >= n4) return;
    float4 v = reinterpret_cast<const float4*>(src)[i];
    __nv_bfloat16 h0 = __float2bfloat16(v.x), h1 = __float2bfloat16(v.y);
    __nv_bfloat16 h2 = __float2bfloat16(v.z), h3 = __float2bfloat16(v.w);
    __nv_bfloat16 l0 = __float2bfloat16(v.x - __bfloat162float(h0));
    __nv_bfloat16 l1 = __float2bfloat16(v.y - __bfloat162float(h1));
    __nv_bfloat16 l2 = __float2bfloat16(v.z - __bfloat162float(h2));
    __nv_bfloat16 l3 = __float2bfloat16(v.w - __bfloat162float(h3));
    uint2 hp, lp;
    hp.x = (uint32_t)__bfloat16_as_ushort(h0) | ((uint32_t)__bfloat16_as_ushort(h1) << 16);
    hp.y = (uint32_t)__bfloat16_as_ushort(h2) | ((uint32_t)__bfloat16_as_ushort(h3) << 16);
    lp.x = (uint32_t)__bfloat16_as_ushort(l0) | ((uint32_t)__bfloat16_as_ushort(l1) << 16);
    lp.y = (uint32_t)__bfloat16_as_ushort(l2) | ((uint32_t)__bfloat16_as_ushort(l3) << 16);
    reinterpret_cast<uint2*>(hi)[i] = hp;
    reinterpret_cast<uint2*>(lo)[i] = lp;
}

// ---------------- split-bf16 NT GEMM via mma.sync ---------------------------
// C[M,N] = A[M,K]*B[N,K]^T (+bias), A/B given as bf16 hi+lo planes.
// CTA tile 128x64, 8 warps (warp tile 32x32), K-step 16, cp.async dbl buffer.
#define SOFF_AL 4096
#define SOFF_BH 8192
#define SOFF_BL 10240
#define SBUF    12288

__device__ __forceinline__ void gemm_issue(
    uint32_t base, const __nv_bfloat16* Agh, const __nv_bfloat16* Agl,
    const __nv_bfloat16* Bgh, const __nv_bfloat16* Bgl,
    int m0, int n0, int kt, int tid)
{
#pragma unroll
    for (int u = 0; u < 3; ++u) {
        int id = tid + u * 256;
        if (id < 256) {
            int row = id >> 1, half = id & 1;
            cpasync16(base + row * 32 + half * 16,
                      Agh + (size_t)(m0 + row) * KDIM + kt + half * 8);
        } else if (id < 512) {
            int r = id - 256, row = r >> 1, half = r & 1;
            cpasync16(base + SOFF_AL + row * 32 + half * 16,
                      Agl + (size_t)(m0 + row) * KDIM + kt + half * 8);
        } else if (id < 640) {
            int r = id - 512, row = r >> 1, half = r & 1;
            cpasync16(base + SOFF_BH + row * 32 + half * 16,
                      Bgh + (size_t)(n0 + row) * KDIM + kt + half * 8);
        } else {
            int r = id - 640, row = r >> 1, half = r & 1;
            cpasync16(base + SOFF_BL + row * 32 + half * 16,
                      Bgl + (size_t)(n0 + row) * KDIM + kt + half * 8);
        }
    }
}

__global__ __launch_bounds__(256)
void gemm_mma(const __nv_bfloat16* __restrict__ Agh,
              const __nv_bfloat16* __restrict__ Agl,
              const __nv_bfloat16* __restrict__ Bgh,
              const __nv_bfloat16* __restrict__ Bgl,
              float* __restrict__ C, const float* __restrict__ bias,
              int Ncols, size_t strideB, size_t strideC)
{
    __shared__ __align__(16) char sm[2 * SBUF];
    const int tid  = threadIdx.x;
    const int w    = tid >> 5, lane = tid & 31;
    const int wr   = w >> 1,  wc   = w & 1;
    const int m0   = blockIdx.y * 128, n0 = blockIdx.x * 64;
    const int z    = blockIdx.z;
    Bgh += (size_t)z * strideB;
    Bgl += (size_t)z * strideB;
    C   += (size_t)z * strideC;
    const uint32_t sb = smem_u32(sm);

    float acc[2][4][4];
#pragma unroll
    for (int i = 0; i < 2; i++)
#pragma unroll
        for (int j = 0; j < 4; j++)
#pragma unroll
            for (int t = 0; t < 4; t++) acc[i][j][t] = 0.f;

    gemm_issue(sb, Agh, Agl, Bgh, Bgl, m0, n0, 0, tid);
    CP_COMMIT();

    const int NK = KDIM / 16;
    const int rA = lane & 15;
    const int cA = (lane >> 4) * 8;
    const int rB = ((lane >> 4) & 1) * 8 + (lane & 7);
    const int cB = ((lane >> 3) & 1) * 8;

    for (int ks = 0; ks < NK; ++ks) {
        const int buf = ks & 1;
        if (ks + 1 < NK) {
            gemm_issue(sb + (buf ^ 1) * SBUF, Agh, Agl, Bgh, Bgl,
                       m0, n0, (ks + 1) * 16, tid);
            CP_COMMIT();
            CP_WAIT(1);
        } else {
            CP_WAIT(0);
        }
        __syncthreads();

        const uint32_t base = sb + buf * SBUF;
        uint32_t aH[2][4], aL[2][4], bH[4][2], bL[4][2];
#pragma unroll
        for (int mi = 0; mi < 2; ++mi) {
            uint32_t addr = base + (uint32_t)((wr * 32 + mi * 16 + rA) * 32 + cA * 2);
            ldsm4(aH[mi], addr);
            ldsm4(aL[mi], addr + SOFF_AL);
        }
#pragma unroll
        for (int njj = 0; njj < 2; ++njj) {
            uint32_t addr = base + SOFF_BH
                          + (uint32_t)((wc * 32 + njj * 16 + rB) * 32 + cB * 2);
            uint32_t r[4];
            ldsm4(r, addr);
            bH[njj * 2][0] = r[0]; bH[njj * 2][1] = r[1];
            bH[njj * 2 + 1][0] = r[2]; bH[njj * 2 + 1][1] = r[3];
            ldsm4(r, addr + (SOFF_BL - SOFF_BH));
            bL[njj * 2][0] = r[0]; bL[njj * 2][1] = r[1];
            bL[njj * 2 + 1][0] = r[2]; bL[njj * 2 + 1][1] = r[3];
        }
#pragma unroll
        for (int mi = 0; mi < 2; ++mi)
#pragma unroll
            for (int nj = 0; nj < 4; ++nj) {
                mma16816(acc[mi][nj], aH[mi], bH[nj]);
                mma16816(acc[mi][nj], aH[mi], bL[nj]);
                mma16816(acc[mi][nj], aL[mi], bH[nj]);
            }
        __syncthreads();
    }

    // epilogue
#pragma unroll
    for (int mi = 0; mi < 2; ++mi) {
        int gr = m0 + wr * 32 + mi * 16 + (lane >> 2);
#pragma unroll
        for (int nj = 0; nj < 4; ++nj) {
            int gc = n0 + wc * 32 + nj * 8 + (lane & 3) * 2;
            float2 v0, v1;
            v0.x = acc[mi][nj][0]; v0.y = acc[mi][nj][1];
            v1.x = acc[mi][nj][2]; v1.y = acc[mi][nj][3];
            if (bias) {
                float b0 = bias[gc], b1 = bias[gc + 1];
                v0.x += b0; v0.y += b1; v1.x += b0; v1.y += b1;
            }
            *reinterpret_cast<float2*>(C + (size_t)gr * Ncols + gc) = v0;
            *reinterpret_cast<float2*>(C + (size_t)(gr + 8) * Ncols + gc) = v1;
        }
    }
}

// ---------------- SPD log-projection (tiled, 1x global traffic) -------------
__global__ __launch_bounds__(256)
void lproj2(const float* __restrict__ src, const float* __restrict__ w,
            const float* __restrict__ bias, float* __restrict__ larr,
            float* __restrict__ l2arr)
{
    __shared__ float s_w[RK][HD];
    __shared__ float s_b[RK];
    __shared__ float s_q[128][HD + 1];

    const int bid  = blockIdx.x;
    const int bh   = bid >> 3;
    const int tile = bid & 7;
    const int b    = bh / NH;
    const int h    = bh - b * NH;
    const int tid  = threadIdx.x;

    ((float*)s_w)[tid]       = w[tid & 511];
    ((float*)s_w)[tid + 256] = w[(tid + 256) & 511];
    if (tid < RK) s_b[tid] = bias[tid];

    const float* base = src + ((size_t)(b * SEQ) + tile * 128) * DIMC + h * HD;
#pragma unroll
    for (int u = 0; u < 8; ++u) {
        int s   = tid + u * 256;
        int row = s >> 4;
        int c4  = (s & 15) << 2;
        float4 v = *reinterpret_cast<const float4*>(base + (size_t)row * DIMC + c4);
        s_q[row][c4 + 0] = v.x; s_q[row][c4 + 1] = v.y;
        s_q[row][c4 + 2] = v.z; s_q[row][c4 + 3] = v.w;
    }
    __syncthreads();

    const int token = tid >> 1;
    const int r0    = (tid & 1) * 4;
    float z0 = s_b[r0 + 0], z1 = s_b[r0 + 1], z2 = s_b[r0 + 2], z3 = s_b[r0 + 3];
#pragma unroll
    for (int d = 0; d < HD; ++d) {
        float q = s_q[token][d];
        z0 = fmaf(q, s_w[r0 + 0][d], z0);
        z1 = fmaf(q, s_w[r0 + 1][d], z1);
        z2 = fmaf(q, s_w[r0 + 2][d], z2);
        z3 = fmaf(q, s_w[r0 + 3][d], z3);
    }
    float lv[4];
    float zz[4] = {z0, z1, z2, z3};
    float s2 = 0.f;
#pragma unroll
    for (int i = 0; i < 4; ++i) {
        float z = zz[i];
        float sp = (z > 20.f) ? z : log1pf(expf(z));
        float l = logf(sp + 1e-6f + 1e-8f);
        lv[i] = l;
        s2 = fmaf(l, l, s2);
    }
    s2 += __shfl_xor_sync(0xffffffffu, s2, 1);

    const size_t t = (size_t)bh * SEQ + tile * 128 + token;
    float4 st = make_float4(lv[0], lv[1], lv[2], lv[3]);
    *reinterpret_cast<float4*>(larr + t * RK + r0) = st;
    if ((tid & 1) == 0) l2arr[t] = s2;
}

// ---------------- fused geodesic attention (flash-style, no max tracking) --
// Writes ctx directly as bf16 hi/lo planes for the output GEMM.
__global__ __launch_bounds__(128)
void attn_kernel()
{
    __shared__ float4 s_v4 [64][16];
    __shared__ float4 s_lk4[64][2];
    __shared__ float  s_lk2[64];

    const int qb  = blockIdx.x;
    const int bh  = blockIdx.y;
    const int b   = bh / NH;
    const int h   = bh - b * NH;
    const int tid = threadIdx.x;
    const int n   = qb * 128 + tid;

    const float* Vp  = g_qkv + (size_t)2 * MTOT * DIMC
                     + (size_t)(b * SEQ) * DIMC + h * HD;
    const float* Lk  = g_lk + (size_t)bh * SEQ * RK;
    const float* Lk2 = g_lk2 + (size_t)bh * SEQ;

    const float* lqp = g_lq + (size_t)bh * SEQ * RK + (size_t)n * RK;
    float4 lqa = *(const float4*)(lqp);
    float4 lqb = *(const float4*)(lqp + 4);
    float lq2 = lqa.x * lqa.x + lqa.y * lqa.y + lqa.z * lqa.z + lqa.w * lqa.w
              + lqb.x * lqb.x + lqb.y * lqb.y + lqb.z * lqb.z + lqb.w * lqb.w;

    float4 o4[16];
#pragma unroll
    for (int i = 0; i < 16; i++) o4[i] = make_float4(0.f, 0.f, 0.f, 0.f);
    float lsum = 0.f;
    const float CEXP = -0.125f * 1.4426950408889634f;

    for (int kt = 0; kt < 16; ++kt) {
        int key0 = kt * 64;
        {
            int key = tid >> 1, rp = tid & 1;
            s_lk4[key][rp] = *(const float4*)(Lk + (size_t)(key0 + key) * RK + rp * 4);
            if (tid < 64) s_lk2[tid] = Lk2[key0 + tid];
        }
#pragma unroll
        for (int u = 0; u < 8; u++) {
            int f = tid + u * 128;
            int key = f >> 4, d4 = f & 15;
            s_v4[key][d4] = *(const float4*)(Vp + (size_t)(key0 + key) * DIMC + d4 * 4);
        }
        __syncthreads();

#pragma unroll 2
        for (int j = 0; j < 64; j++) {
            float4 k0 = s_lk4[j][0];
            float4 k1 = s_lk4[j][1];
            float dot = lqa.x * k0.x;
            dot = fmaf(lqa.y, k0.y, dot);
            dot = fmaf(lqa.z, k0.z, dot);
            dot = fmaf(lqa.w, k0.w, dot);
            dot = fmaf(lqb.x, k1.x, dot);
            dot = fmaf(lqb.y, k1.y, dot);
            dot = fmaf(lqb.z, k1.z, dot);
            dot = fmaf(lqb.w, k1.w, dot);
            float d2 = fmaxf(fmaf(-2.f, dot, lq2 + s_lk2[j]), 1e-12f);
            float dist = d2 * rsqa(d2);
            float p = ex2a(CEXP * dist);
            lsum += p;
            const float4* vr = s_v4[j];
#pragma unroll
            for (int t2 = 0; t2 < 16; t2++) {
                float4 vv = vr[t2];
                o4[t2].x = fmaf(p, vv.x, o4[t2].x);
                o4[t2].y = fmaf(p, vv.y, o4[t2].y);
                o4[t2].z = fmaf(p, vv.z, o4[t2].z);
                o4[t2].w = fmaf(p, vv.w, o4[t2].w);
            }
        }
        __syncthreads();
    }

    float inv = 1.0f / lsum;
    size_t obase = (size_t)(b * SEQ + n) * DIMC + h * HD;
#pragma unroll
    for (int t2 = 0; t2 < 16; t2++) {
        float4 r = o4[t2];
        r.x *= inv; r.y *= inv; r.z *= inv; r.w *= inv;
        __nv_bfloat16 h0 = __float2bfloat16(r.x), h1 = __float2bfloat16(r.y);
        __nv_bfloat16 h2 = __float2bfloat16(r.z), h3 = __float2bfloat16(r.w);
        __nv_bfloat16 l0 = __float2bfloat16(r.x - __bfloat162float(h0));
        __nv_bfloat16 l1 = __float2bfloat16(r.y - __bfloat162float(h1));
        __nv_bfloat16 l2 = __float2bfloat16(r.z - __bfloat162float(h2));
        __nv_bfloat16 l3 = __float2bfloat16(r.w - __bfloat162float(h3));
        uint2 hp, lp;
        hp.x = (uint32_t)__bfloat16_as_ushort(h0) | ((uint32_t)__bfloat16_as_ushort(h1) << 16);
        hp.y = (uint32_t)__bfloat16_as_ushort(h2) | ((uint32_t)__bfloat16_as_ushort(h3) << 16);
        lp.x = (uint32_t)__bfloat16_as_ushort(l0) | ((uint32_t)__bfloat16_as_ushort(l1) << 16);
        lp.y = (uint32_t)__bfloat16_as_ushort(l2) | ((uint32_t)__bfloat16_as_ushort(l3) << 16);
        *reinterpret_cast<uint2*>(g_ch + obase + t2 * 4) = hp;
        *reinterpret_cast<uint2*>(g_cl + obase + t2 * 4) = lp;
    }
}

// ---------------- KL term (deterministic two-stage reduction) --------------
__global__ __launch_bounds__(256)
void kl_partial(const float* __restrict__ m0, const float* __restrict__ l0,
                const float* __restrict__ m1, const float* __restrict__ l1,
                const float* __restrict__ m2, const float* __restrict__ l2,
                const float* __restrict__ m3, const float* __restrict__ l3)
{
    const int PER = DIMC * DIMC;
    const int TOT = 4 * PER;
    float s = 0.f;
    for (int idx = blockIdx.x * blockDim.x + threadIdx.x; idx < TOT;
         idx += gridDim.x * blockDim.x) {
        int p   = idx / PER;
        int off = idx - p * PER;
        const float* mp = (p == 0) ? m0 : (p == 1) ? m1 : (p == 2) ? m2 : m3;
        const float* lp = (p == 0) ? l0 : (p == 1) ? l1 : (p == 2) ? l2 : l3;
        float mu = mp[off], ls = lp[off];
        s += 0.5f * (expf(2.f * ls) + mu * mu - 1.f - 2.f * ls);
    }
    __shared__ float red[256];
    red[threadIdx.x] = s;
    __syncthreads();
    for (int w = 128; w > 0; w >>= 1) {
        if (threadIdx.x < w) red[threadIdx.x] += red[threadIdx.x + w];
        __syncthreads();
    }
    if (threadIdx.x == 0) g_klpart[blockIdx.x] = red[0];
}

__global__ void kl_final(float* __restrict__ dst)
{
    __shared__ float red[256];
    red[threadIdx.x] = g_klpart[threadIdx.x];
    __syncthreads();
    for (int w = 128; w > 0; w >>= 1) {
        if (threadIdx.x < w) red[threadIdx.x] += red[threadIdx.x + w];
        __syncthreads();
    }
    if (threadIdx.x == 0) *dst = red[0];
}

// ---------------- launcher -------------------------------------------------
extern "C" void kernel_launch(void* const* d_in, const int* in_sizes, int n_in,
                              void* d_out, int out_size)
{
    const float* x     = (const float*)d_in[0];
    const float* wq_mu = (const float*)d_in[1];
    const float* wq_ls = (const float*)d_in[2];
    const float* wk_mu = (const float*)d_in[3];
    const float* wk_ls = (const float*)d_in[4];
    const float* wv_mu = (const float*)d_in[5];
    const float* wv_ls = (const float*)d_in[6];
    const float* wo_mu = (const float*)d_in[7];
    const float* wo_ls = (const float*)d_in[8];
    const float* wo_b  = (const float*)d_in[9];
    const float* sq_w  = (const float*)d_in[10];
    const float* sq_b  = (const float*)d_in[11];
    const float* sk_w  = (const float*)d_in[12];
    const float* sk_b  = (const float*)d_in[13];
    float* out = (float*)d_out;

    float *qkv_d, *lq_d, *lk_d, *lq2_d, *lk2_d;
    __nv_bfloat16 *xh_d, *xl_d, *wh_d, *wl_d, *woh_d, *wol_d, *ch_d, *cl_d;
    cudaGetSymbolAddress((void**)&qkv_d, g_qkv);
    cudaGetSymbolAddress((void**)&lq_d,  g_lq);
    cudaGetSymbolAddress((void**)&lk_d,  g_lk);
    cudaGetSymbolAddress((void**)&lq2_d, g_lq2);
    cudaGetSymbolAddress((void**)&lk2_d, g_lk2);
    cudaGetSymbolAddress((void**)&xh_d,  g_xh);
    cudaGetSymbolAddress((void**)&xl_d,  g_xl);
    cudaGetSymbolAddress((void**)&wh_d,  g_wh);
    cudaGetSymbolAddress((void**)&wl_d,  g_wl);
    cudaGetSymbolAddress((void**)&woh_d, g_woh);
    cudaGetSymbolAddress((void**)&wol_d, g_wol);
    cudaGetSymbolAddress((void**)&ch_d,  g_ch);
    cudaGetSymbolAddress((void**)&cl_d,  g_cl);

    const int PER = DIMC * DIMC;           // 589824

    // splits
    split_kernel<<<(MTOT * DIMC / 4 + 255) / 256, 256>>>(x, xh_d, xl_d, MTOT * DIMC / 4);
    split_kernel<<<(PER / 4 + 255) / 256, 256>>>(wq_mu, wh_d + 0 * (size_t)PER, wl_d + 0 * (size_t)PER, PER / 4);
    split_kernel<<<(PER / 4 + 255) / 256, 256>>>(wk_mu, wh_d + 1 * (size_t)PER, wl_d + 1 * (size_t)PER, PER / 4);
    split_kernel<<<(PER / 4 + 255) / 256, 256>>>(wv_mu, wh_d + 2 * (size_t)PER, wl_d + 2 * (size_t)PER, PER / 4);
    split_kernel<<<(PER / 4 + 255) / 256, 256>>>(wo_mu, woh_d, wol_d, PER / 4);

    // fused QKV GEMM (z selects wq/wk/wv plane and q/k/v output plane)
    gemm_mma<<<dim3(DIMC / 64, MTOT / 128, 3), 256>>>(
        xh_d, xl_d, wh_d, wl_d, qkv_d, nullptr,
        DIMC, (size_t)PER, (size_t)MTOT * DIMC);

    lproj2<<<BH * 8, 256>>>(qkv_d + 0 * (size_t)MTOT * DIMC, sq_w, sq_b, lq_d, lq2_d);
    lproj2<<<BH * 8, 256>>>(qkv_d + 1 * (size_t)MTOT * DIMC, sk_w, sk_b, lk_d, lk2_d);

    attn_kernel<<<dim3(SEQ / 128, BH), 128>>>();

    gemm_mma<<<dim3(DIMC / 64, MTOT / 128, 1), 256>>>(
        ch_d, cl_d, woh_d, wol_d, out, wo_b, DIMC, 0, 0);

    kl_partial<<<256, 256>>>(wq_mu, wq_ls, wk_mu, wk_ls,
                             wv_mu, wv_ls, wo_mu, wo_ls);
    if (out_size > MTOT * DIMC) {
        kl_final<<<1, 256>>>(out + (size_t)out_size - 1);
    }
}

// round 6
// speedup vs baseline: 2.4693x; 1.3360x over previous
#include <cuda_runtime.h>
#include <cuda_bf16.h>
#include <cstdint>
#include <math.h>

#define BATCH 4
#define SEQ   1024
#define DIMC  768
#define NH    12
#define HD    64
#define RK    8
#define MTOT  (BATCH*SEQ)     /* 4096 */
#define BH    (BATCH*NH)      /* 48   */
#define KDIM  768

// ---------------- scratch (device globals; no allocation allowed) ----------
__device__ __align__(16) float g_qkv[3*MTOT*DIMC];     // q,k,v planes
__device__ __align__(16) float g_lq [BH*SEQ*RK];
__device__ __align__(16) float g_lk [BH*SEQ*RK];
__device__ __align__(16) float g_lq2[BH*SEQ];
__device__ __align__(16) float g_lk2[BH*SEQ];
__device__ __align__(16) float g_sv [BH*HD];           // sum_k V per (bh,d)
__device__ float g_klpart[256];
// bf16 hi/lo planes
__device__ __align__(16) __nv_bfloat16 g_xh [MTOT*DIMC];
__device__ __align__(16) __nv_bfloat16 g_xl [MTOT*DIMC];
__device__ __align__(16) __nv_bfloat16 g_wh [3*DIMC*DIMC];
__device__ __align__(16) __nv_bfloat16 g_wl [3*DIMC*DIMC];
__device__ __align__(16) __nv_bfloat16 g_woh[DIMC*DIMC];
__device__ __align__(16) __nv_bfloat16 g_wol[DIMC*DIMC];
__device__ __align__(16) __nv_bfloat16 g_ch [MTOT*DIMC];
__device__ __align__(16) __nv_bfloat16 g_cl [MTOT*DIMC];

// ---------------- fast approx helpers --------------------------------------
__device__ __forceinline__ float ex2a(float x) {
    float y; asm("ex2.approx.f32 %0, %1;" : "=f"(y) : "f"(x)); return y;
}
__device__ __forceinline__ float rsqa(float x) {
    float y; asm("rsqrt.approx.f32 %0, %1;" : "=f"(y) : "f"(x)); return y;
}

// ---------------- portable tensor-core primitives (sm_80+) ------------------
__device__ __forceinline__ uint32_t smem_u32(const void* p) {
    uint32_t a;
    asm("{ .reg .u64 t; cvta.to.shared.u64 t, %1; cvt.u32.u64 %0, t; }"
        : "=r"(a) : "l"(p));
    return a;
}
__device__ __forceinline__ void cpasync16(uint32_t dst, const void* src) {
    asm volatile("cp.async.cg.shared.global [%0], [%1], 16;"
                 :: "r"(dst), "l"(src));
}
#define CP_COMMIT() asm volatile("cp.async.commit_group;" ::: "memory")
#define CP_WAIT(n)  asm volatile("cp.async.wait_group %0;" :: "n"(n) : "memory")

__device__ __forceinline__ void ldsm4(uint32_t* r, uint32_t addr) {
    asm volatile("ldmatrix.sync.aligned.m8n8.x4.shared.b16 {%0,%1,%2,%3}, [%4];"
        : "=r"(r[0]), "=r"(r[1]), "=r"(r[2]), "=r"(r[3]) : "r"(addr));
}
__device__ __forceinline__ void ldsm4t(uint32_t* r, uint32_t addr) {
    asm volatile("ldmatrix.sync.aligned.m8n8.x4.trans.shared.b16 {%0,%1,%2,%3}, [%4];"
        : "=r"(r[0]), "=r"(r[1]), "=r"(r[2]), "=r"(r[3]) : "r"(addr));
}
__device__ __forceinline__ void mma16816(float* c, const uint32_t* a,
                                         const uint32_t* b) {
    asm volatile(
        "mma.sync.aligned.m16n8k16.row.col.f32.bf16.bf16.f32 "
        "{%0,%1,%2,%3}, {%4,%5,%6,%7}, {%8,%9}, {%0,%1,%2,%3};"
        : "+f"(c[0]), "+f"(c[1]), "+f"(c[2]), "+f"(c[3])
        : "r"(a[0]), "r"(a[1]), "r"(a[2]), "r"(a[3]), "r"(b[0]), "r"(b[1]));
}

// ---------------- split fp32 -> bf16 hi/lo ----------------------------------
__global__ __launch_bounds__(256)
void split_kernel(const float* __restrict__ src, __nv_bfloat16* __restrict__ hi,
                  __nv_bfloat16* __restrict__ lo, int n4)
{
    int i = blockIdx.x * blockDim.x + threadIdx.x;
    if (i >= n4) return;
    float4 v = reinterpret_cast<const float4*>(src)[i];
    __nv_bfloat16 h0 = __float2bfloat16(v.x), h1 = __float2bfloat16(v.y);
    __nv_bfloat16 h2 = __float2bfloat16(v.z), h3 = __float2bfloat16(v.w);
    __nv_bfloat16 l0 = __float2bfloat16(v.x - __bfloat162float(h0));
    __nv_bfloat16 l1 = __float2bfloat16(v.y - __bfloat162float(h1));
    __nv_bfloat16 l2 = __float2bfloat16(v.z - __bfloat162float(h2));
    __nv_bfloat16 l3 = __float2bfloat16(v.w - __bfloat162float(h3));
    uint2 hp, lp;
    hp.x = (uint32_t)__bfloat16_as_ushort(h0) | ((uint32_t)__bfloat16_as_ushort(h1) << 16);
    hp.y = (uint32_t)__bfloat16_as_ushort(h2) | ((uint32_t)__bfloat16_as_ushort(h3) << 16);
    lp.x = (uint32_t)__bfloat16_as_ushort(l0) | ((uint32_t)__bfloat16_as_ushort(l1) << 16);
    lp.y = (uint32_t)__bfloat16_as_ushort(l2) | ((uint32_t)__bfloat16_as_ushort(l3) << 16);
    reinterpret_cast<uint2*>(hi)[i] = hp;
    reinterpret_cast<uint2*>(lo)[i] = lp;
}

// ---------------- split-bf16 NT GEMM via mma.sync ---------------------------
#define SOFF_AL 4096
#define SOFF_BH 8192
#define SOFF_BL 10240
#define SBUF    12288

__device__ __forceinline__ void gemm_issue(
    uint32_t base, const __nv_bfloat16* Agh, const __nv_bfloat16* Agl,
    const __nv_bfloat16* Bgh, const __nv_bfloat16* Bgl,
    int m0, int n0, int kt, int tid)
{
#pragma unroll
    for (int u = 0; u < 3; ++u) {
        int id = tid + u * 256;
        if (id < 256) {
            int row = id >> 1, half = id & 1;
            cpasync16(base + row * 32 + half * 16,
                      Agh + (size_t)(m0 + row) * KDIM + kt + half * 8);
        } else if (id < 512) {
            int r = id - 256, row = r >> 1, half = r & 1;
            cpasync16(base + SOFF_AL + row * 32 + half * 16,
                      Agl + (size_t)(m0 + row) * KDIM + kt + half * 8);
        } else if (id < 640) {
            int r = id - 512, row = r >> 1, half = r & 1;
            cpasync16(base + SOFF_BH + row * 32 + half * 16,
                      Bgh + (size_t)(n0 + row) * KDIM + kt + half * 8);
        } else {
            int r = id - 640, row = r >> 1, half = r & 1;
            cpasync16(base + SOFF_BL + row * 32 + half * 16,
                      Bgl + (size_t)(n0 + row) * KDIM + kt + half * 8);
        }
    }
}

__global__ __launch_bounds__(256)
void gemm_mma(const __nv_bfloat16* __restrict__ Agh,
              const __nv_bfloat16* __restrict__ Agl,
              const __nv_bfloat16* __restrict__ Bgh,
              const __nv_bfloat16* __restrict__ Bgl,
              float* __restrict__ C, const float* __restrict__ bias,
              int Ncols, size_t strideB, size_t strideC)
{
    __shared__ __align__(16) char sm[2 * SBUF];
    const int tid  = threadIdx.x;
    const int w    = tid >> 5, lane = tid & 31;
    const int wr   = w >> 1,  wc   = w & 1;
    const int m0   = blockIdx.y * 128, n0 = blockIdx.x * 64;
    const int z    = blockIdx.z;
    Bgh += (size_t)z * strideB;
    Bgl += (size_t)z * strideB;
    C   += (size_t)z * strideC;
    const uint32_t sb = smem_u32(sm);

    float acc[2][4][4];
#pragma unroll
    for (int i = 0; i < 2; i++)
#pragma unroll
        for (int j = 0; j < 4; j++)
#pragma unroll
            for (int t = 0; t < 4; t++) acc[i][j][t] = 0.f;

    gemm_issue(sb, Agh, Agl, Bgh, Bgl, m0, n0, 0, tid);
    CP_COMMIT();

    const int NK = KDIM / 16;
    const int rA = lane & 15;
    const int cA = (lane >> 4) * 8;
    const int rB = ((lane >> 4) & 1) * 8 + (lane & 7);
    const int cB = ((lane >> 3) & 1) * 8;

    for (int ks = 0; ks < NK; ++ks) {
        const int buf = ks & 1;
        if (ks + 1 < NK) {
            gemm_issue(sb + (buf ^ 1) * SBUF, Agh, Agl, Bgh, Bgl,
                       m0, n0, (ks + 1) * 16, tid);
            CP_COMMIT();
            CP_WAIT(1);
        } else {
            CP_WAIT(0);
        }
        __syncthreads();

        const uint32_t base = sb + buf * SBUF;
        uint32_t aH[2][4], aL[2][4], bH[4][2], bL[4][2];
#pragma unroll
        for (int mi = 0; mi < 2; ++mi) {
            uint32_t addr = base + (uint32_t)((wr * 32 + mi * 16 + rA) * 32 + cA * 2);
            ldsm4(aH[mi], addr);
            ldsm4(aL[mi], addr + SOFF_AL);
        }
#pragma unroll
        for (int njj = 0; njj < 2; ++njj) {
            uint32_t addr = base + SOFF_BH
                          + (uint32_t)((wc * 32 + njj * 16 + rB) * 32 + cB * 2);
            uint32_t r[4];
            ldsm4(r, addr);
            bH[njj * 2][0] = r[0]; bH[njj * 2][1] = r[1];
            bH[njj * 2 + 1][0] = r[2]; bH[njj * 2 + 1][1] = r[3];
            ldsm4(r, addr + (SOFF_BL - SOFF_BH));
            bL[njj * 2][0] = r[0]; bL[njj * 2][1] = r[1];
            bL[njj * 2 + 1][0] = r[2]; bL[njj * 2 + 1][1] = r[3];
        }
#pragma unroll
        for (int mi = 0; mi < 2; ++mi)
#pragma unroll
            for (int nj = 0; nj < 4; ++nj) {
                mma16816(acc[mi][nj], aH[mi], bH[nj]);
                mma16816(acc[mi][nj], aH[mi], bL[nj]);
                mma16816(acc[mi][nj], aL[mi], bH[nj]);
            }
        __syncthreads();
    }

#pragma unroll
    for (int mi = 0; mi < 2; ++mi) {
        int gr = m0 + wr * 32 + mi * 16 + (lane >> 2);
#pragma unroll
        for (int nj = 0; nj < 4; ++nj) {
            int gc = n0 + wc * 32 + nj * 8 + (lane & 3) * 2;
            float2 v0, v1;
            v0.x = acc[mi][nj][0]; v0.y = acc[mi][nj][1];
            v1.x = acc[mi][nj][2]; v1.y = acc[mi][nj][3];
            if (bias) {
                float b0 = bias[gc], b1 = bias[gc + 1];
                v0.x += b0; v0.y += b1; v1.x += b0; v1.y += b1;
            }
            *reinterpret_cast<float2*>(C + (size_t)gr * Ncols + gc) = v0;
            *reinterpret_cast<float2*>(C + (size_t)(gr + 8) * Ncols + gc) = v1;
        }
    }
}

// ---------------- SPD log-projection ----------------------------------------
__global__ __launch_bounds__(256)
void lproj2(const float* __restrict__ src, const float* __restrict__ w,
            const float* __restrict__ bias, float* __restrict__ larr,
            float* __restrict__ l2arr)
{
    __shared__ float s_w[RK][HD];
    __shared__ float s_b[RK];
    __shared__ float s_q[128][HD + 1];

    const int bid  = blockIdx.x;
    const int bh   = bid >> 3;
    const int tile = bid & 7;
    const int b    = bh / NH;
    const int h    = bh - b * NH;
    const int tid  = threadIdx.x;

    ((float*)s_w)[tid]       = w[tid & 511];
    ((float*)s_w)[tid + 256] = w[(tid + 256) & 511];
    if (tid < RK) s_b[tid] = bias[tid];

    const float* base = src + ((size_t)(b * SEQ) + tile * 128) * DIMC + h * HD;
#pragma unroll
    for (int u = 0; u < 8; ++u) {
        int s   = tid + u * 256;
        int row = s >> 4;
        int c4  = (s & 15) << 2;
        float4 v = *reinterpret_cast<const float4*>(base + (size_t)row * DIMC + c4);
        s_q[row][c4 + 0] = v.x; s_q[row][c4 + 1] = v.y;
        s_q[row][c4 + 2] = v.z; s_q[row][c4 + 3] = v.w;
    }
    __syncthreads();

    const int token = tid >> 1;
    const int r0    = (tid & 1) * 4;
    float z0 = s_b[r0 + 0], z1 = s_b[r0 + 1], z2 = s_b[r0 + 2], z3 = s_b[r0 + 3];
#pragma unroll
    for (int d = 0; d < HD; ++d) {
        float q = s_q[token][d];
        z0 = fmaf(q, s_w[r0 + 0][d], z0);
        z1 = fmaf(q, s_w[r0 + 1][d], z1);
        z2 = fmaf(q, s_w[r0 + 2][d], z2);
        z3 = fmaf(q, s_w[r0 + 3][d], z3);
    }
    float lv[4];
    float zz[4] = {z0, z1, z2, z3};
    float s2 = 0.f;
#pragma unroll
    for (int i = 0; i < 4; ++i) {
        float z = zz[i];
        float sp = (z > 20.f) ? z : log1pf(expf(z));
        float l = logf(sp + 1e-6f + 1e-8f);
        lv[i] = l;
        s2 = fmaf(l, l, s2);
    }
    s2 += __shfl_xor_sync(0xffffffffu, s2, 1);

    const size_t t = (size_t)bh * SEQ + tile * 128 + token;
    float4 st = make_float4(lv[0], lv[1], lv[2], lv[3]);
    *reinterpret_cast<float4*>(larr + t * RK + r0) = st;
    if ((tid & 1) == 0) l2arr[t] = s2;
}

// ---------------- SV precompute: g_sv[bh][d] = sum_k V[b,k,h,d] -------------
__global__ __launch_bounds__(256)
void svsum_kernel()
{
    __shared__ float part[4][HD];
    const int bh = blockIdx.x;
    const int b = bh / NH, h = bh - b * NH;
    const int tid = threadIdx.x;
    const int d = tid & 63, seg = tid >> 6;
    const float* Vp = g_qkv + (size_t)2 * MTOT * DIMC
                    + (size_t)(b * SEQ) * DIMC + h * HD + d;
    float s = 0.f;
    for (int k = seg * 256; k < seg * 256 + 256; ++k)
        s += Vp[(size_t)k * DIMC];
    part[seg][d] = s;
    __syncthreads();
    if (tid < HD)
        g_sv[bh * HD + tid] = part[0][tid] + part[1][tid]
                            + part[2][tid] + part[3][tid];
}

// ---------------- geodesic attention: u = 1-p trick + bf16 MMA for U.V ------
// out_row = (SV - sum_k u*v) / (1024 - sum_k u),  u = 1 - exp(-scale*dist)
#define AKT 64
#define UP  72   /* bf16 pitch: 144B rows -> conflict-free ldmatrix */

__global__ __launch_bounds__(256)
void attn_mma()
{
    __shared__ __align__(16) float s_lk[AKT][8];
    __shared__ float s_lk2[AKT];
    __shared__ float s_sv[HD];
    __shared__ float s_linv[128];
    __shared__ __align__(16) __nv_bfloat16 s_v[AKT][UP];
    __shared__ __align__(16) __nv_bfloat16 s_u[128][UP];

    const int qb = blockIdx.x, bh = blockIdx.y;
    const int b = bh / NH, h = bh - b * NH;
    const int tid = threadIdx.x, lane = tid & 31, w = tid >> 5;
    const int q = tid >> 1, par = tid & 1;
    const int n = qb * 128 + q;

    const float* lqp = g_lq + ((size_t)bh * SEQ + n) * RK;
    float4 lqa = *(const float4*)(lqp);
    float4 lqb = *(const float4*)(lqp + 4);
    float lq2 = g_lq2[(size_t)bh * SEQ + n];

    if (tid < HD) s_sv[tid] = g_sv[bh * HD + tid];

    const float* Vp  = g_qkv + (size_t)2 * MTOT * DIMC
                     + (size_t)(b * SEQ) * DIMC + h * HD;
    const float* Lk  = g_lk + (size_t)bh * SEQ * RK;
    const float* Lk2 = g_lk2 + (size_t)bh * SEQ;

    float acc[8][4];
#pragma unroll
    for (int i = 0; i < 8; i++)
#pragma unroll
        for (int j = 0; j < 4; j++) acc[i][j] = 0.f;
    float usum = 0.f;
    const float CEXP = -0.125f * 1.4426950408889634f;  // -SCALE*log2(e)

    for (int kt = 0; kt < SEQ / AKT; ++kt) {
        const int key0 = kt * AKT;
        __syncthreads();
        // load lk tile + lk2
        if (tid < 128) {
            int key = tid >> 1, p2 = tid & 1;
            *(float4*)&s_lk[key][p2 * 4] =
                *(const float4*)(Lk + (size_t)(key0 + key) * RK + p2 * 4);
        } else if (tid < 192) {
            s_lk2[tid - 128] = Lk2[key0 + tid - 128];
        }
        // load V tile, convert to bf16
#pragma unroll
        for (int u2 = 0; u2 < 4; ++u2) {
            int s = tid + u2 * 256;
            int key = s >> 4, d4 = (s & 15) * 4;
            float4 v = *(const float4*)(Vp + (size_t)(key0 + key) * DIMC + d4);
            uint2 pk;
            pk.x = (uint32_t)__bfloat16_as_ushort(__float2bfloat16(v.x))
                 | ((uint32_t)__bfloat16_as_ushort(__float2bfloat16(v.y)) << 16);
            pk.y = (uint32_t)__bfloat16_as_ushort(__float2bfloat16(v.z))
                 | ((uint32_t)__bfloat16_as_ushort(__float2bfloat16(v.w)) << 16);
            *reinterpret_cast<uint2*>(&s_v[key][d4]) = pk;
        }
        __syncthreads();

        // score phase: thread q = tid>>1 handles keys j = par + 2*jj
#pragma unroll 4
        for (int jj = 0; jj < 32; ++jj) {
            int j = par + 2 * jj;
            float4 k0 = *(const float4*)&s_lk[j][0];
            float4 k1 = *(const float4*)&s_lk[j][4];
            float dot = lqa.x * k0.x;
            dot = fmaf(lqa.y, k0.y, dot);
            dot = fmaf(lqa.z, k0.z, dot);
            dot = fmaf(lqa.w, k0.w, dot);
            dot = fmaf(lqb.x, k1.x, dot);
            dot = fmaf(lqb.y, k1.y, dot);
            dot = fmaf(lqb.z, k1.z, dot);
            dot = fmaf(lqb.w, k1.w, dot);
            float d2 = fmaxf(fmaf(-2.f, dot, lq2 + s_lk2[j]), 1e-12f);
            float dist = d2 * rsqa(d2);
            float u = 1.f - ex2a(CEXP * dist);
            usum += u;
            float up = __shfl_xor_sync(0xffffffffu, u, 1);
            if (par == 0) {
                uint32_t pk = (uint32_t)__bfloat16_as_ushort(__float2bfloat16(u))
                   | ((uint32_t)__bfloat16_as_ushort(__float2bfloat16(up)) << 16);
                *reinterpret_cast<uint32_t*>(&s_u[q][2 * jj]) = pk;
            }
        }
        __syncthreads();

        // MMA phase: warp w handles q rows [16w, 16w+16)
        const int rL = lane & 15, cL = (lane >> 4) * 8;
#pragma unroll
        for (int ks = 0; ks < 4; ++ks) {
            uint32_t a[4];
            ldsm4(a, smem_u32(&s_u[16 * w + rL][16 * ks + cL]));
#pragma unroll
            for (int nc = 0; nc < 4; ++nc) {
                uint32_t r[4];
                ldsm4t(r, smem_u32(&s_v[16 * ks + rL][16 * nc + cL]));
                mma16816(acc[2 * nc],     a, r);
                mma16816(acc[2 * nc + 1], a, r + 2);
            }
        }
    }

    float tot = usum + __shfl_xor_sync(0xffffffffu, usum, 1);
    if (par == 0) s_linv[q] = 1.f / (1024.f - tot);
    __syncthreads();

    // epilogue: out = (SV - acc) * inv ; write hi/lo bf16 ctx planes
    const int rlo = 16 * w + (lane >> 2);
    const float ilo = s_linv[rlo], ihi = s_linv[rlo + 8];
    const size_t rowb = (size_t)(b * SEQ + qb * 128) * DIMC + h * HD;
#pragma unroll
    for (int nc = 0; nc < 8; ++nc) {
        int c = 8 * nc + (lane & 3) * 2;
        float sv0 = s_sv[c], sv1 = s_sv[c + 1];
        float o00 = (sv0 - acc[nc][0]) * ilo;
        float o01 = (sv1 - acc[nc][1]) * ilo;
        float o10 = (sv0 - acc[nc][2]) * ihi;
        float o11 = (sv1 - acc[nc][3]) * ihi;
        __nv_bfloat16 h00 = __float2bfloat16(o00), h01 = __float2bfloat16(o01);
        __nv_bfloat16 h10 = __float2bfloat16(o10), h11 = __float2bfloat16(o11);
        __nv_bfloat16 l00 = __float2bfloat16(o00 - __bfloat162float(h00));
        __nv_bfloat16 l01 = __float2bfloat16(o01 - __bfloat162float(h01));
        __nv_bfloat16 l10 = __float2bfloat16(o10 - __bfloat162float(h10));
        __nv_bfloat16 l11 = __float2bfloat16(o11 - __bfloat162float(h11));
        size_t a0 = rowb + (size_t)rlo * DIMC + c;
        size_t a1 = rowb + (size_t)(rlo + 8) * DIMC + c;
        *reinterpret_cast<uint32_t*>(g_ch + a0) =
            (uint32_t)__bfloat16_as_ushort(h00) | ((uint32_t)__bfloat16_as_ushort(h01) << 16);
        *reinterpret_cast<uint32_t*>(g_cl + a0) =
            (uint32_t)__bfloat16_as_ushort(l00) | ((uint32_t)__bfloat16_as_ushort(l01) << 16);
        *reinterpret_cast<uint32_t*>(g_ch + a1) =
            (uint32_t)__bfloat16_as_ushort(h10) | ((uint32_t)__bfloat16_as_ushort(h11) << 16);
        *reinterpret_cast<uint32_t*>(g_cl + a1) =
            (uint32_t)__bfloat16_as_ushort(l10) | ((uint32_t)__bfloat16_as_ushort(l11) << 16);
    }
}

// ---------------- KL term (deterministic two-stage reduction) --------------
__global__ __launch_bounds__(256)
void kl_partial(const float* __restrict__ m0, const float* __restrict__ l0,
                const float* __restrict__ m1, const float* __restrict__ l1,
                const float* __restrict__ m2, const float* __restrict__ l2,
                const float* __restrict__ m3, const float* __restrict__ l3)
{
    const int PER = DIMC * DIMC;
    const int TOT = 4 * PER;
    float s = 0.f;
    for (int idx = blockIdx.x * blockDim.x + threadIdx.x; idx < TOT;
         idx += gridDim.x * blockDim.x) {
        int p   = idx / PER;
        int off = idx - p * PER;
        const float* mp = (p == 0) ? m0 : (p == 1) ? m1 : (p == 2) ? m2 : m3;
        const float* lp = (p == 0) ? l0 : (p == 1) ? l1 : (p == 2) ? l2 : l3;
        float mu = mp[off], ls = lp[off];
        s += 0.5f * (expf(2.f * ls) + mu * mu - 1.f - 2.f * ls);
    }
    __shared__ float red[256];
    red[threadIdx.x] = s;
    __syncthreads();
    for (int w = 128; w > 0; w >>= 1) {
        if (threadIdx.x < w) red[threadIdx.x] += red[threadIdx.x + w];
        __syncthreads();
    }
    if (threadIdx.x == 0) g_klpart[blockIdx.x] = red[0];
}

__global__ void kl_final(float* __restrict__ dst)
{
    __shared__ float red[256];
    red[threadIdx.x] = g_klpart[threadIdx.x];
    __syncthreads();
    for (int w = 128; w > 0; w >>= 1) {
        if (threadIdx.x < w) red[threadIdx.x] += red[threadIdx.x + w];
        __syncthreads();
    }
    if (threadIdx.x == 0) *dst = red[0];
}

// ---------------- launcher -------------------------------------------------
extern "C" void kernel_launch(void* const* d_in, const int* in_sizes, int n_in,
                              void* d_out, int out_size)
{
    const float* x     = (const float*)d_in[0];
    const float* wq_mu = (const float*)d_in[1];
    const float* wq_ls = (const float*)d_in[2];
    const float* wk_mu = (const float*)d_in[3];
    const float* wk_ls = (const float*)d_in[4];
    const float* wv_mu = (const float*)d_in[5];
    const float* wv_ls = (const float*)d_in[6];
    const float* wo_mu = (const float*)d_in[7];
    const float* wo_ls = (const float*)d_in[8];
    const float* wo_b  = (const float*)d_in[9];
    const float* sq_w  = (const float*)d_in[10];
    const float* sq_b  = (const float*)d_in[11];
    const float* sk_w  = (const float*)d_in[12];
    const float* sk_b  = (const float*)d_in[13];
    float* out = (float*)d_out;

    float *qkv_d, *lq_d, *lk_d, *lq2_d, *lk2_d;
    __nv_bfloat16 *xh_d, *xl_d, *wh_d, *wl_d, *woh_d, *wol_d, *ch_d, *cl_d;
    cudaGetSymbolAddress((void**)&qkv_d, g_qkv);
    cudaGetSymbolAddress((void**)&lq_d,  g_lq);
    cudaGetSymbolAddress((void**)&lk_d,  g_lk);
    cudaGetSymbolAddress((void**)&lq2_d, g_lq2);
    cudaGetSymbolAddress((void**)&lk2_d, g_lk2);
    cudaGetSymbolAddress((void**)&xh_d,  g_xh);
    cudaGetSymbolAddress((void**)&xl_d,  g_xl);
    cudaGetSymbolAddress((void**)&wh_d,  g_wh);
    cudaGetSymbolAddress((void**)&wl_d,  g_wl);
    cudaGetSymbolAddress((void**)&woh_d, g_woh);
    cudaGetSymbolAddress((void**)&wol_d, g_wol);
    cudaGetSymbolAddress((void**)&ch_d,  g_ch);
    cudaGetSymbolAddress((void**)&cl_d,  g_cl);

    const int PER = DIMC * DIMC;

    split_kernel<<<(MTOT * DIMC / 4 + 255) / 256, 256>>>(x, xh_d, xl_d, MTOT * DIMC / 4);
    split_kernel<<<(PER / 4 + 255) / 256, 256>>>(wq_mu, wh_d + 0 * (size_t)PER, wl_d + 0 * (size_t)PER, PER / 4);
    split_kernel<<<(PER / 4 + 255) / 256, 256>>>(wk_mu, wh_d + 1 * (size_t)PER, wl_d + 1 * (size_t)PER, PER / 4);
    split_kernel<<<(PER / 4 + 255) / 256, 256>>>(wv_mu, wh_d + 2 * (size_t)PER, wl_d + 2 * (size_t)PER, PER / 4);
    split_kernel<<<(PER / 4 + 255) / 256, 256>>>(wo_mu, woh_d, wol_d, PER / 4);

    gemm_mma<<<dim3(DIMC / 64, MTOT / 128, 3), 256>>>(
        xh_d, xl_d, wh_d, wl_d, qkv_d, nullptr,
        DIMC, (size_t)PER, (size_t)MTOT * DIMC);

    lproj2<<<BH * 8, 256>>>(qkv_d + 0 * (size_t)MTOT * DIMC, sq_w, sq_b, lq_d, lq2_d);
    lproj2<<<BH * 8, 256>>>(qkv_d + 1 * (size_t)MTOT * DIMC, sk_w, sk_b, lk_d, lk2_d);
    svsum_kernel<<<BH, 256>>>();

    attn_mma<<<dim3(SEQ / 128, BH), 256>>>();

    gemm_mma<<<dim3(DIMC / 64, MTOT / 128, 1), 256>>>(
        ch_d, cl_d, woh_d, wol_d, out, wo_b, DIMC, 0, 0);

    kl_partial<<<256, 256>>>(wq_mu, wq_ls, wk_mu, wk_ls,
                             wv_mu, wv_ls, wo_mu, wo_ls);
    if (out_size > MTOT * DIMC) {
        kl_final<<<1, 256>>>(out + (size_t)out_size - 1);
    }
}

// round 7
// speedup vs baseline: 3.5710x; 1.4462x over previous
#include <cuda_runtime.h>
#include <cuda.h>
#include <cuda_bf16.h>
#include <cstdint>
#include <math.h>

#define BATCH 4
#define SEQ   1024
#define DIMC  768
#define NH    12
#define HD    64
#define RK    8
#define MTOT  (BATCH*SEQ)     /* 4096 */
#define BH    (BATCH*NH)      /* 48   */
#define KDIM  768

// ---------------- scratch (device globals; no allocation allowed) ----------
__device__ __align__(16) float g_qkv[3*MTOT*DIMC];     // q,k,v planes
__device__ __align__(16) float g_lq [BH*SEQ*RK];
__device__ __align__(16) float g_lk [BH*SEQ*RK];
__device__ __align__(16) float g_lq2[BH*SEQ];
__device__ __align__(16) float g_lk2[BH*SEQ];
__device__ __align__(16) float g_sv [BH*HD];
__device__ float g_klpart[256];
__device__ __align__(1024) __nv_bfloat16 g_xh [MTOT*DIMC];
__device__ __align__(1024) __nv_bfloat16 g_xl [MTOT*DIMC];
__device__ __align__(1024) __nv_bfloat16 g_wh [3*DIMC*DIMC];
__device__ __align__(1024) __nv_bfloat16 g_wl [3*DIMC*DIMC];
__device__ __align__(1024) __nv_bfloat16 g_woh[DIMC*DIMC];
__device__ __align__(1024) __nv_bfloat16 g_wol[DIMC*DIMC];
__device__ __align__(1024) __nv_bfloat16 g_ch [MTOT*DIMC];
__device__ __align__(1024) __nv_bfloat16 g_cl [MTOT*DIMC];

// ---------------- fast approx helpers --------------------------------------
__device__ __forceinline__ float ex2a(float x) {
    float y; asm("ex2.approx.f32 %0, %1;" : "=f"(y) : "f"(x)); return y;
}
__device__ __forceinline__ float rsqa(float x) {
    float y; asm("rsqrt.approx.f32 %0, %1;" : "=f"(y) : "f"(x)); return y;
}

// ---------------- smem / mma primitives -------------------------------------
__device__ __forceinline__ uint32_t smem_u32(const void* p) {
    uint32_t a;
    asm("{ .reg .u64 t; cvta.to.shared.u64 t, %1; cvt.u32.u64 %0, t; }"
        : "=r"(a) : "l"(p));
    return a;
}
__device__ __forceinline__ void ldsm4(uint32_t* r, uint32_t addr) {
    asm volatile("ldmatrix.sync.aligned.m8n8.x4.shared.b16 {%0,%1,%2,%3}, [%4];"
        : "=r"(r[0]), "=r"(r[1]), "=r"(r[2]), "=r"(r[3]) : "r"(addr));
}
__device__ __forceinline__ void ldsm4t(uint32_t* r, uint32_t addr) {
    asm volatile("ldmatrix.sync.aligned.m8n8.x4.trans.shared.b16 {%0,%1,%2,%3}, [%4];"
        : "=r"(r[0]), "=r"(r[1]), "=r"(r[2]), "=r"(r[3]) : "r"(addr));
}
__device__ __forceinline__ void mma16816(float* c, const uint32_t* a,
                                         const uint32_t* b) {
    asm volatile(
        "mma.sync.aligned.m16n8k16.row.col.f32.bf16.bf16.f32 "
        "{%0,%1,%2,%3}, {%4,%5,%6,%7}, {%8,%9}, {%0,%1,%2,%3};"
        : "+f"(c[0]), "+f"(c[1]), "+f"(c[2]), "+f"(c[3])
        : "r"(a[0]), "r"(a[1]), "r"(a[2]), "r"(a[3]), "r"(b[0]), "r"(b[1]));
}
#define SW128(x) ((x) ^ (((x) >> 3) & 0x70))

// ---------------- TMA / mbarrier --------------------------------------------
#define MBAR_INIT(mb, c) asm volatile("mbarrier.init.shared.b64 [%0], %1;" :: "r"((uint32_t)(mb)), "r"((uint32_t)(c)) : "memory")
#define MBAR_EXPECT_TX(mb, tx) asm volatile("mbarrier.arrive.expect_tx.shared.b64 _, [%0], %1;" :: "r"((uint32_t)(mb)), "r"((uint32_t)(tx)) : "memory")
__device__ __forceinline__ void mbar_wait(uint32_t mb, uint32_t ph) {
    asm volatile(
        "{\n\t.reg .pred P1;\n\t"
        "WL_%=:\n\t"
        "mbarrier.try_wait.parity.acquire.cta.shared::cta.b64 P1, [%0], %1, 0x989680;\n\t"
        "@P1 bra.uni WD_%=;\n\t"
        "bra.uni WL_%=;\n\t"
        "WD_%=:\n\t}"
        :: "r"(mb), "r"(ph) : "memory");
}
__device__ __forceinline__ void tma2d(uint32_t dst, const void* map,
                                      int x, int y, uint32_t mbar) {
    asm volatile(
        "cp.async.bulk.tensor.2d.shared::cta.global.tile.mbarrier::complete_tx::bytes "
        "[%0], [%1, {%2, %3}], [%4];"
        :: "r"(dst), "l"(map), "r"(x), "r"(y), "r"(mbar) : "memory");
}

// ---------------- split fp32 -> bf16 hi/lo ----------------------------------
__global__ __launch_bounds__(256)
void split_kernel(const float* __restrict__ src, __nv_bfloat16* __restrict__ hi,
                  __nv_bfloat16* __restrict__ lo, int n4)
{
    int i = blockIdx.x * blockDim.x + threadIdx.x;
    if (i >= n4) return;
    float4 v = reinterpret_cast<const float4*>(src)[i];
    __nv_bfloat16 h0 = __float2bfloat16(v.x), h1 = __float2bfloat16(v.y);
    __nv_bfloat16 h2 = __float2bfloat16(v.z), h3 = __float2bfloat16(v.w);
    __nv_bfloat16 l0 = __float2bfloat16(v.x - __bfloat162float(h0));
    __nv_bfloat16 l1 = __float2bfloat16(v.y - __bfloat162float(h1));
    __nv_bfloat16 l2 = __float2bfloat16(v.z - __bfloat162float(h2));
    __nv_bfloat16 l3 = __float2bfloat16(v.w - __bfloat162float(h3));
    uint2 hp, lp;
    hp.x = (uint32_t)__bfloat16_as_ushort(h0) | ((uint32_t)__bfloat16_as_ushort(h1) << 16);
    hp.y = (uint32_t)__bfloat16_as_ushort(h2) | ((uint32_t)__bfloat16_as_ushort(h3) << 16);
    lp.x = (uint32_t)__bfloat16_as_ushort(l0) | ((uint32_t)__bfloat16_as_ushort(l1) << 16);
    lp.y = (uint32_t)__bfloat16_as_ushort(l2) | ((uint32_t)__bfloat16_as_ushort(l3) << 16);
    reinterpret_cast<uint2*>(hi)[i] = hp;
    reinterpret_cast<uint2*>(lo)[i] = lp;
}

// ---------------- TMA-fed split-bf16 NT GEMM --------------------------------
// C[M,N] = A[M,K]*B[N,K]^T (+bias).  Tile 128x64, K-chunk 64, 2-stage TMA.
// smem stage: Ah 16K | Al 16K | Bh 8K | Bl 8K  = 48K  (SW128 layout, 128B rows)
#define GST   49152
#define GSA_L 16384
#define GSB_H 32768
#define GSB_L 40960
#define GEMM_DSMEM (2 * GST + 1024)

__global__ __launch_bounds__(256)
void gemm_tma(const __grid_constant__ CUtensorMap mAh,
              const __grid_constant__ CUtensorMap mAl,
              const __grid_constant__ CUtensorMap mBh,
              const __grid_constant__ CUtensorMap mBl,
              float* __restrict__ C, const float* __restrict__ bias,
              int Ncols, size_t strideC)
{
    extern __shared__ char dsm[];
    __shared__ __align__(8) uint64_t mbarrier_s[2];
    const int tid = threadIdx.x;
    const int w = tid >> 5, lane = tid & 31;
    const int wr = w >> 1, wc = w & 1;
    const int m0 = blockIdx.y * 128, n0 = blockIdx.x * 64;
    const int z = blockIdx.z;
    const int yB = z * DIMC + n0;
    C += (size_t)z * strideC;

    const uint32_t sb = (smem_u32(dsm) + 1023u) & ~1023u;
    const uint32_t mb0 = smem_u32(&mbarrier_s[0]);
    const uint32_t mb1 = smem_u32(&mbarrier_s[1]);

    if (tid == 0) { MBAR_INIT(mb0, 1); MBAR_INIT(mb1, 1); }
    __syncthreads();

    if (tid == 0) {
#pragma unroll
        for (int s = 0; s < 2; ++s) {
            uint32_t mb = s ? mb1 : mb0;
            uint32_t base = sb + s * GST;
            MBAR_EXPECT_TX(mb, GST);
            tma2d(base,          &mAh, s * 64, m0, mb);
            tma2d(base + GSA_L,  &mAl, s * 64, m0, mb);
            tma2d(base + GSB_H,  &mBh, s * 64, yB, mb);
            tma2d(base + GSB_L,  &mBl, s * 64, yB, mb);
        }
    }

    float acc[2][4][4];
#pragma unroll
    for (int i = 0; i < 2; i++)
#pragma unroll
        for (int j = 0; j < 4; j++)
#pragma unroll
            for (int t = 0; t < 4; t++) acc[i][j][t] = 0.f;

    const int rA = lane & 15;
    const int cA = (lane >> 4) * 8;
    const int rB = ((lane >> 4) & 1) * 8 + (lane & 7);
    const int cB = ((lane >> 3) & 1) * 8;
    const int NCH = KDIM / 64;   // 12

    for (int c = 0; c < NCH; ++c) {
        const int b = c & 1;
        mbar_wait(b ? mb1 : mb0, (c >> 1) & 1);
        const uint32_t base = sb + b * GST;
#pragma unroll
        for (int ks = 0; ks < 4; ++ks) {
            uint32_t aH[2][4], aL[2][4], bH[4][2], bL[4][2];
#pragma unroll
            for (int mi = 0; mi < 2; ++mi) {
                uint32_t off = (uint32_t)((wr * 32 + mi * 16 + rA) * 128
                             + (ks * 16 + cA) * 2);
                uint32_t sw = SW128(off);
                ldsm4(aH[mi], base + sw);
                ldsm4(aL[mi], base + GSA_L + sw);
            }
#pragma unroll
            for (int njj = 0; njj < 2; ++njj) {
                uint32_t off = (uint32_t)((wc * 32 + njj * 16 + rB) * 128
                             + (ks * 16 + cB) * 2);
                uint32_t sw = SW128(off);
                uint32_t r[4];
                ldsm4(r, base + GSB_H + sw);
                bH[njj * 2][0] = r[0]; bH[njj * 2][1] = r[1];
                bH[njj * 2 + 1][0] = r[2]; bH[njj * 2 + 1][1] = r[3];
                ldsm4(r, base + GSB_L + sw);
                bL[njj * 2][0] = r[0]; bL[njj * 2][1] = r[1];
                bL[njj * 2 + 1][0] = r[2]; bL[njj * 2 + 1][1] = r[3];
            }
#pragma unroll
            for (int mi = 0; mi < 2; ++mi)
#pragma unroll
                for (int nj = 0; nj < 4; ++nj) {
                    mma16816(acc[mi][nj], aH[mi], bH[nj]);
                    mma16816(acc[mi][nj], aH[mi], bL[nj]);
                    mma16816(acc[mi][nj], aL[mi], bH[nj]);
                }
        }
        __syncthreads();
        if (c + 2 < NCH && tid == 0) {
            uint32_t mb = b ? mb1 : mb0;
            uint32_t base2 = sb + b * GST;
            MBAR_EXPECT_TX(mb, GST);
            tma2d(base2,         &mAh, (c + 2) * 64, m0, mb);
            tma2d(base2 + GSA_L, &mAl, (c + 2) * 64, m0, mb);
            tma2d(base2 + GSB_H, &mBh, (c + 2) * 64, yB, mb);
            tma2d(base2 + GSB_L, &mBl, (c + 2) * 64, yB, mb);
        }
    }

#pragma unroll
    for (int mi = 0; mi < 2; ++mi) {
        int gr = m0 + wr * 32 + mi * 16 + (lane >> 2);
#pragma unroll
        for (int nj = 0; nj < 4; ++nj) {
            int gc = n0 + wc * 32 + nj * 8 + (lane & 3) * 2;
            float2 v0, v1;
            v0.x = acc[mi][nj][0]; v0.y = acc[mi][nj][1];
            v1.x = acc[mi][nj][2]; v1.y = acc[mi][nj][3];
            if (bias) {
                float b0 = bias[gc], b1 = bias[gc + 1];
                v0.x += b0; v0.y += b1; v1.x += b0; v1.y += b1;
            }
            *reinterpret_cast<float2*>(C + (size_t)gr * Ncols + gc) = v0;
            *reinterpret_cast<float2*>(C + (size_t)(gr + 8) * Ncols + gc) = v1;
        }
    }
}

// ---------------- SPD log-projection ----------------------------------------
__global__ __launch_bounds__(256)
void lproj2(const float* __restrict__ src, const float* __restrict__ w,
            const float* __restrict__ bias, float* __restrict__ larr,
            float* __restrict__ l2arr)
{
    __shared__ float s_w[RK][HD];
    __shared__ float s_b[RK];
    __shared__ float s_q[128][HD + 1];

    const int bid  = blockIdx.x;
    const int bh   = bid >> 3;
    const int tile = bid & 7;
    const int b    = bh / NH;
    const int h    = bh - b * NH;
    const int tid  = threadIdx.x;

    ((float*)s_w)[tid]       = w[tid & 511];
    ((float*)s_w)[tid + 256] = w[(tid + 256) & 511];
    if (tid < RK) s_b[tid] = bias[tid];

    const float* base = src + ((size_t)(b * SEQ) + tile * 128) * DIMC + h * HD;
#pragma unroll
    for (int u = 0; u < 8; ++u) {
        int s   = tid + u * 256;
        int row = s >> 4;
        int c4  = (s & 15) << 2;
        float4 v = *reinterpret_cast<const float4*>(base + (size_t)row * DIMC + c4);
        s_q[row][c4 + 0] = v.x; s_q[row][c4 + 1] = v.y;
        s_q[row][c4 + 2] = v.z; s_q[row][c4 + 3] = v.w;
    }
    __syncthreads();

    const int token = tid >> 1;
    const int r0    = (tid & 1) * 4;
    float z0 = s_b[r0 + 0], z1 = s_b[r0 + 1], z2 = s_b[r0 + 2], z3 = s_b[r0 + 3];
#pragma unroll
    for (int d = 0; d < HD; ++d) {
        float q = s_q[token][d];
        z0 = fmaf(q, s_w[r0 + 0][d], z0);
        z1 = fmaf(q, s_w[r0 + 1][d], z1);
        z2 = fmaf(q, s_w[r0 + 2][d], z2);
        z3 = fmaf(q, s_w[r0 + 3][d], z3);
    }
    float lv[4];
    float zz[4] = {z0, z1, z2, z3};
    float s2 = 0.f;
#pragma unroll
    for (int i = 0; i < 4; ++i) {
        float z = zz[i];
        float sp = (z > 20.f) ? z : log1pf(expf(z));
        float l = logf(sp + 1e-6f + 1e-8f);
        lv[i] = l;
        s2 = fmaf(l, l, s2);
    }
    s2 += __shfl_xor_sync(0xffffffffu, s2, 1);

    const size_t t = (size_t)bh * SEQ + tile * 128 + token;
    float4 st = make_float4(lv[0], lv[1], lv[2], lv[3]);
    *reinterpret_cast<float4*>(larr + t * RK + r0) = st;
    if ((tid & 1) == 0) l2arr[t] = s2;
}

// ---------------- SV precompute ---------------------------------------------
__global__ __launch_bounds__(256)
void svsum_kernel()
{
    __shared__ float part[4][HD];
    const int bh = blockIdx.x;
    const int b = bh / NH, h = bh - b * NH;
    const int tid = threadIdx.x;
    const int d = tid & 63, seg = tid >> 6;
    const float* Vp = g_qkv + (size_t)2 * MTOT * DIMC
                    + (size_t)(b * SEQ) * DIMC + h * HD + d;
    float s = 0.f;
    for (int k = seg * 256; k < seg * 256 + 256; ++k)
        s += Vp[(size_t)k * DIMC];
    part[seg][d] = s;
    __syncthreads();
    if (tid < HD)
        g_sv[bh * HD + tid] = part[0][tid] + part[1][tid]
                            + part[2][tid] + part[3][tid];
}

// ---------------- geodesic attention (u = 1-p + bf16 MMA) -------------------
#define AKT 64
#define UP  72

__global__ __launch_bounds__(256)
void attn_mma()
{
    __shared__ __align__(16) float s_lk[AKT][8];
    __shared__ float s_lk2[AKT];
    __shared__ float s_sv[HD];
    __shared__ float s_linv[128];
    __shared__ __align__(16) __nv_bfloat16 s_v[AKT][UP];
    __shared__ __align__(16) __nv_bfloat16 s_u[128][UP];

    const int qb = blockIdx.x, bh = blockIdx.y;
    const int b = bh / NH, h = bh - b * NH;
    const int tid = threadIdx.x, lane = tid & 31, w = tid >> 5;
    const int q = tid >> 1, par = tid & 1;
    const int n = qb * 128 + q;

    const float* lqp = g_lq + ((size_t)bh * SEQ + n) * RK;
    float4 lqa = *(const float4*)(lqp);
    float4 lqb = *(const float4*)(lqp + 4);
    float lq2 = g_lq2[(size_t)bh * SEQ + n];

    if (tid < HD) s_sv[tid] = g_sv[bh * HD + tid];

    const float* Vp  = g_qkv + (size_t)2 * MTOT * DIMC
                     + (size_t)(b * SEQ) * DIMC + h * HD;
    const float* Lk  = g_lk + (size_t)bh * SEQ * RK;
    const float* Lk2 = g_lk2 + (size_t)bh * SEQ;

    float acc[8][4];
#pragma unroll
    for (int i = 0; i < 8; i++)
#pragma unroll
        for (int j = 0; j < 4; j++) acc[i][j] = 0.f;
    float usum = 0.f;
    const float CEXP = -0.125f * 1.4426950408889634f;

    for (int kt = 0; kt < SEQ / AKT; ++kt) {
        const int key0 = kt * AKT;
        __syncthreads();
        if (tid < 128) {
            int key = tid >> 1, p2 = tid & 1;
            *(float4*)&s_lk[key][p2 * 4] =
                *(const float4*)(Lk + (size_t)(key0 + key) * RK + p2 * 4);
        } else if (tid < 192) {
            s_lk2[tid - 128] = Lk2[key0 + tid - 128];
        }
#pragma unroll
        for (int u2 = 0; u2 < 4; ++u2) {
            int s = tid + u2 * 256;
            int key = s >> 4, d4 = (s & 15) * 4;
            float4 v = *(const float4*)(Vp + (size_t)(key0 + key) * DIMC + d4);
            uint2 pk;
            pk.x = (uint32_t)__bfloat16_as_ushort(__float2bfloat16(v.x))
                 | ((uint32_t)__bfloat16_as_ushort(__float2bfloat16(v.y)) << 16);
            pk.y = (uint32_t)__bfloat16_as_ushort(__float2bfloat16(v.z))
                 | ((uint32_t)__bfloat16_as_ushort(__float2bfloat16(v.w)) << 16);
            *reinterpret_cast<uint2*>(&s_v[key][d4]) = pk;
        }
        __syncthreads();

#pragma unroll 4
        for (int jj = 0; jj < 32; ++jj) {
            int j = par + 2 * jj;
            float4 k0 = *(const float4*)&s_lk[j][0];
            float4 k1 = *(const float4*)&s_lk[j][4];
            float dot = lqa.x * k0.x;
            dot = fmaf(lqa.y, k0.y, dot);
            dot = fmaf(lqa.z, k0.z, dot);
            dot = fmaf(lqa.w, k0.w, dot);
            dot = fmaf(lqb.x, k1.x, dot);
            dot = fmaf(lqb.y, k1.y, dot);
            dot = fmaf(lqb.z, k1.z, dot);
            dot = fmaf(lqb.w, k1.w, dot);
            float d2 = fmaxf(fmaf(-2.f, dot, lq2 + s_lk2[j]), 1e-12f);
            float dist = d2 * rsqa(d2);
            float u = 1.f - ex2a(CEXP * dist);
            usum += u;
            float up = __shfl_xor_sync(0xffffffffu, u, 1);
            if (par == 0) {
                uint32_t pk = (uint32_t)__bfloat16_as_ushort(__float2bfloat16(u))
                   | ((uint32_t)__bfloat16_as_ushort(__float2bfloat16(up)) << 16);
                *reinterpret_cast<uint32_t*>(&s_u[q][2 * jj]) = pk;
            }
        }
        __syncthreads();

        const int rL = lane & 15, cL = (lane >> 4) * 8;
#pragma unroll
        for (int ks = 0; ks < 4; ++ks) {
            uint32_t a[4];
            ldsm4(a, smem_u32(&s_u[16 * w + rL][16 * ks + cL]));
#pragma unroll
            for (int nc = 0; nc < 4; ++nc) {
                uint32_t r[4];
                ldsm4t(r, smem_u32(&s_v[16 * ks + rL][16 * nc + cL]));
                mma16816(acc[2 * nc],     a, r);
                mma16816(acc[2 * nc + 1], a, r + 2);
            }
        }
    }

    float tot = usum + __shfl_xor_sync(0xffffffffu, usum, 1);
    if (par == 0) s_linv[q] = 1.f / (1024.f - tot);
    __syncthreads();

    const int rlo = 16 * w + (lane >> 2);
    const float ilo = s_linv[rlo], ihi = s_linv[rlo + 8];
    const size_t rowb = (size_t)(b * SEQ + qb * 128) * DIMC + h * HD;
#pragma unroll
    for (int nc = 0; nc < 8; ++nc) {
        int c = 8 * nc + (lane & 3) * 2;
        float sv0 = s_sv[c], sv1 = s_sv[c + 1];
        float o00 = (sv0 - acc[nc][0]) * ilo;
        float o01 = (sv1 - acc[nc][1]) * ilo;
        float o10 = (sv0 - acc[nc][2]) * ihi;
        float o11 = (sv1 - acc[nc][3]) * ihi;
        __nv_bfloat16 h00 = __float2bfloat16(o00), h01 = __float2bfloat16(o01);
        __nv_bfloat16 h10 = __float2bfloat16(o10), h11 = __float2bfloat16(o11);
        __nv_bfloat16 l00 = __float2bfloat16(o00 - __bfloat162float(h00));
        __nv_bfloat16 l01 = __float2bfloat16(o01 - __bfloat162float(h01));
        __nv_bfloat16 l10 = __float2bfloat16(o10 - __bfloat162float(h10));
        __nv_bfloat16 l11 = __float2bfloat16(o11 - __bfloat162float(h11));
        size_t a0 = rowb + (size_t)rlo * DIMC + c;
        size_t a1 = rowb + (size_t)(rlo + 8) * DIMC + c;
        *reinterpret_cast<uint32_t*>(g_ch + a0) =
            (uint32_t)__bfloat16_as_ushort(h00) | ((uint32_t)__bfloat16_as_ushort(h01) << 16);
        *reinterpret_cast<uint32_t*>(g_cl + a0) =
            (uint32_t)__bfloat16_as_ushort(l00) | ((uint32_t)__bfloat16_as_ushort(l01) << 16);
        *reinterpret_cast<uint32_t*>(g_ch + a1) =
            (uint32_t)__bfloat16_as_ushort(h10) | ((uint32_t)__bfloat16_as_ushort(h11) << 16);
        *reinterpret_cast<uint32_t*>(g_cl + a1) =
            (uint32_t)__bfloat16_as_ushort(l10) | ((uint32_t)__bfloat16_as_ushort(l11) << 16);
    }
}

// ---------------- KL term (vectorized deterministic reduction) --------------
__global__ __launch_bounds__(256)
void kl_partial(const float* __restrict__ m0, const float* __restrict__ l0,
                const float* __restrict__ m1, const float* __restrict__ l1,
                const float* __restrict__ m2, const float* __restrict__ l2,
                const float* __restrict__ m3, const float* __restrict__ l3)
{
    const int PER4 = DIMC * DIMC / 4;
    const int TOT4 = 4 * PER4;
    const float L2E2 = 2.0f * 1.4426950408889634f;
    float s = 0.f;
    for (int i4 = blockIdx.x * blockDim.x + threadIdx.x; i4 < TOT4;
         i4 += gridDim.x * blockDim.x) {
        int p   = i4 / PER4;
        int off = i4 - p * PER4;
        const float* mp = (p == 0) ? m0 : (p == 1) ? m1 : (p == 2) ? m2 : m3;
        const float* lp = (p == 0) ? l0 : (p == 1) ? l1 : (p == 2) ? l2 : l3;
        float4 mu = reinterpret_cast<const float4*>(mp)[off];
        float4 ls = reinterpret_cast<const float4*>(lp)[off];
        s += 0.5f * (ex2a(L2E2 * ls.x) + mu.x * mu.x - 1.f - 2.f * ls.x);
        s += 0.5f * (ex2a(L2E2 * ls.y) + mu.y * mu.y - 1.f - 2.f * ls.y);
        s += 0.5f * (ex2a(L2E2 * ls.z) + mu.z * mu.z - 1.f - 2.f * ls.z);
        s += 0.5f * (ex2a(L2E2 * ls.w) + mu.w * mu.w - 1.f - 2.f * ls.w);
    }
    __shared__ float red[256];
    red[threadIdx.x] = s;
    __syncthreads();
    for (int w = 128; w > 0; w >>= 1) {
        if (threadIdx.x < w) red[threadIdx.x] += red[threadIdx.x + w];
        __syncthreads();
    }
    if (threadIdx.x == 0) g_klpart[blockIdx.x] = red[0];
}

__global__ void kl_final(float* __restrict__ dst)
{
    __shared__ float red[256];
    red[threadIdx.x] = g_klpart[threadIdx.x];
    __syncthreads();
    for (int w = 128; w > 0; w >>= 1) {
        if (threadIdx.x < w) red[threadIdx.x] += red[threadIdx.x + w];
        __syncthreads();
    }
    if (threadIdx.x == 0) *dst = red[0];
}

// ---------------- host: tensor map encoding ---------------------------------
typedef CUresult (*PFN_tmEnc)(CUtensorMap*, CUtensorMapDataType, cuuint32_t,
                              void*, const cuuint64_t*, const cuuint64_t*,
                              const cuuint32_t*, const cuuint32_t*,
                              CUtensorMapInterleave, CUtensorMapSwizzle,
                              CUtensorMapL2promotion, CUtensorMapFloatOOBfill);

static void encode_map(PFN_tmEnc fn, CUtensorMap* m, void* ptr,
                       unsigned long long rows, unsigned boxRows)
{
    cuuint64_t dims[2]    = {(cuuint64_t)KDIM, (cuuint64_t)rows};
    cuuint64_t strides[1] = {(cuuint64_t)KDIM * 2};
    cuuint32_t box[2]     = {64u, boxRows};
    cuuint32_t es[2]      = {1u, 1u};
    fn(m, CU_TENSOR_MAP_DATA_TYPE_BFLOAT16, 2, ptr, dims, strides, box, es,
       CU_TENSOR_MAP_INTERLEAVE_NONE, CU_TENSOR_MAP_SWIZZLE_128B,
       CU_TENSOR_MAP_L2_PROMOTION_L2_128B, CU_TENSOR_MAP_FLOAT_OOB_FILL_NONE);
}

// ---------------- launcher -------------------------------------------------
extern "C" void kernel_launch(void* const* d_in, const int* in_sizes, int n_in,
                              void* d_out, int out_size)
{
    const float* x     = (const float*)d_in[0];
    const float* wq_mu = (const float*)d_in[1];
    const float* wq_ls = (const float*)d_in[2];
    const float* wk_mu = (const float*)d_in[3];
    const float* wk_ls = (const float*)d_in[4];
    const float* wv_mu = (const float*)d_in[5];
    const float* wv_ls = (const float*)d_in[6];
    const float* wo_mu = (const float*)d_in[7];
    const float* wo_ls = (const float*)d_in[8];
    const float* wo_b  = (const float*)d_in[9];
    const float* sq_w  = (const float*)d_in[10];
    const float* sq_b  = (const float*)d_in[11];
    const float* sk_w  = (const float*)d_in[12];
    const float* sk_b  = (const float*)d_in[13];
    float* out = (float*)d_out;

    float *qkv_d, *lq_d, *lk_d, *lq2_d, *lk2_d;
    __nv_bfloat16 *xh_d, *xl_d, *wh_d, *wl_d, *woh_d, *wol_d, *ch_d, *cl_d;
    cudaGetSymbolAddress((void**)&qkv_d, g_qkv);
    cudaGetSymbolAddress((void**)&lq_d,  g_lq);
    cudaGetSymbolAddress((void**)&lk_d,  g_lk);
    cudaGetSymbolAddress((void**)&lq2_d, g_lq2);
    cudaGetSymbolAddress((void**)&lk2_d, g_lk2);
    cudaGetSymbolAddress((void**)&xh_d,  g_xh);
    cudaGetSymbolAddress((void**)&xl_d,  g_xl);
    cudaGetSymbolAddress((void**)&wh_d,  g_wh);
    cudaGetSymbolAddress((void**)&wl_d,  g_wl);
    cudaGetSymbolAddress((void**)&woh_d, g_woh);
    cudaGetSymbolAddress((void**)&wol_d, g_wol);
    cudaGetSymbolAddress((void**)&ch_d,  g_ch);
    cudaGetSymbolAddress((void**)&cl_d,  g_cl);

    static PFN_tmEnc tmEnc = nullptr;
    if (!tmEnc) {
        cudaDriverEntryPointQueryResult qr;
        cudaGetDriverEntryPoint("cuTensorMapEncodeTiled", (void**)&tmEnc,
                                cudaEnableDefault, &qr);
    }
    CUtensorMap mXh, mXl, mWh, mWl, mCh, mCl, mOh, mOl;
    encode_map(tmEnc, &mXh, xh_d,  MTOT,     128);
    encode_map(tmEnc, &mXl, xl_d,  MTOT,     128);
    encode_map(tmEnc, &mWh, wh_d,  3 * DIMC, 64);
    encode_map(tmEnc, &mWl, wl_d,  3 * DIMC, 64);
    encode_map(tmEnc, &mCh, ch_d,  MTOT,     128);
    encode_map(tmEnc, &mCl, cl_d,  MTOT,     128);
    encode_map(tmEnc, &mOh, woh_d, DIMC,     64);
    encode_map(tmEnc, &mOl, wol_d, DIMC,     64);

    cudaFuncSetAttribute(gemm_tma, cudaFuncAttributeMaxDynamicSharedMemorySize,
                         GEMM_DSMEM);

    const int PER = DIMC * DIMC;

    split_kernel<<<(MTOT * DIMC / 4 + 255) / 256, 256>>>(x, xh_d, xl_d, MTOT * DIMC / 4);
    split_kernel<<<(PER / 4 + 255) / 256, 256>>>(wq_mu, wh_d + 0 * (size_t)PER, wl_d + 0 * (size_t)PER, PER / 4);
    split_kernel<<<(PER / 4 + 255) / 256, 256>>>(wk_mu, wh_d + 1 * (size_t)PER, wl_d + 1 * (size_t)PER, PER / 4);
    split_kernel<<<(PER / 4 + 255) / 256, 256>>>(wv_mu, wh_d + 2 * (size_t)PER, wl_d + 2 * (size_t)PER, PER / 4);
    split_kernel<<<(PER / 4 + 255) / 256, 256>>>(wo_mu, woh_d, wol_d, PER / 4);

    gemm_tma<<<dim3(DIMC / 64, MTOT / 128, 3), 256, GEMM_DSMEM>>>(
        mXh, mXl, mWh, mWl, qkv_d, nullptr, DIMC, (size_t)MTOT * DIMC);

    lproj2<<<BH * 8, 256>>>(qkv_d + 0 * (size_t)MTOT * DIMC, sq_w, sq_b, lq_d, lq2_d);
    lproj2<<<BH * 8, 256>>>(qkv_d + 1 * (size_t)MTOT * DIMC, sk_w, sk_b, lk_d, lk2_d);
    svsum_kernel<<<BH, 256>>>();

    attn_mma<<<dim3(SEQ / 128, BH), 256>>>();

    gemm_tma<<<dim3(DIMC / 64, MTOT / 128, 1), 256, GEMM_DSMEM>>>(
        mCh, mCl, mOh, mOl, out, wo_b, DIMC, 0);

    kl_partial<<<256, 256>>>(wq_mu, wq_ls, wk_mu, wk_ls,
                             wv_mu, wv_ls, wo_mu, wo_ls);
    if (out_size > MTOT * DIMC) {
        kl_final<<<1, 256>>>(out + (size_t)out_size - 1);
    }
}

// round 9
// speedup vs baseline: 4.4084x; 1.2345x over previous
#include <cuda_runtime.h>
#include <cuda.h>
#include <cuda_bf16.h>
#include <cstdint>
#include <math.h>

#define BATCH 4
#define SEQ   1024
#define DIMC  768
#define NH    12
#define HD    64
#define RK    8
#define MTOT  (BATCH*SEQ)     /* 4096 */
#define BH    (BATCH*NH)      /* 48   */
#define KDIM  768
#define PER   (DIMC*DIMC)

// ---------------- scratch (device globals; no allocation allowed) ----------
__device__ __align__(16) float g_qkv[3*MTOT*DIMC];     // q,k,v planes
__device__ __align__(16) __nv_bfloat16 g_lqp[BH*SEQ*16]; // [hi8|lo8] scaled
__device__ __align__(16) __nv_bfloat16 g_lkp[BH*SEQ*16];
__device__ __align__(16) float g_lq2[BH*SEQ];            // scaled |lq'|^2
__device__ __align__(16) float g_lk2[BH*SEQ];
__device__ __align__(16) float g_sv [BH*HD];
__device__ float g_klpart[256];
__device__ __align__(1024) __nv_bfloat16 g_xh [MTOT*DIMC];
__device__ __align__(1024) __nv_bfloat16 g_xl [MTOT*DIMC];
__device__ __align__(1024) __nv_bfloat16 g_wh [3*PER];
__device__ __align__(1024) __nv_bfloat16 g_wl [3*PER];
__device__ __align__(1024) __nv_bfloat16 g_woh[PER];
__device__ __align__(1024) __nv_bfloat16 g_wol[PER];
__device__ __align__(1024) __nv_bfloat16 g_ch [MTOT*DIMC];
__device__ __align__(1024) __nv_bfloat16 g_cl [MTOT*DIMC];

// ---------------- fast approx helpers --------------------------------------
__device__ __forceinline__ float ex2a(float x) {
    float y; asm("ex2.approx.f32 %0, %1;" : "=f"(y) : "f"(x)); return y;
}
__device__ __forceinline__ float sqa(float x) {
    float y; asm("sqrt.approx.f32 %0, %1;" : "=f"(y) : "f"(x)); return y;
}
__device__ __forceinline__ uint32_t pack_bf16x2(float lo, float hi) {
    uint32_t r;
    asm("cvt.rn.bf16x2.f32 %0, %1, %2;" : "=r"(r) : "f"(hi), "f"(lo));
    return r;
}

// ---------------- smem / mma primitives -------------------------------------
__device__ __forceinline__ uint32_t smem_u32(const void* p) {
    uint32_t a;
    asm("{ .reg .u64 t; cvta.to.shared.u64 t, %1; cvt.u32.u64 %0, t; }"
        : "=r"(a) : "l"(p));
    return a;
}
__device__ __forceinline__ void ldsm4(uint32_t* r, uint32_t addr) {
    asm volatile("ldmatrix.sync.aligned.m8n8.x4.shared.b16 {%0,%1,%2,%3}, [%4];"
        : "=r"(r[0]), "=r"(r[1]), "=r"(r[2]), "=r"(r[3]) : "r"(addr));
}
__device__ __forceinline__ void ldsm4t(uint32_t* r, uint32_t addr) {
    asm volatile("ldmatrix.sync.aligned.m8n8.x4.trans.shared.b16 {%0,%1,%2,%3}, [%4];"
        : "=r"(r[0]), "=r"(r[1]), "=r"(r[2]), "=r"(r[3]) : "r"(addr));
}
__device__ __forceinline__ void mma16816(float* c, const uint32_t* a,
                                         const uint32_t* b) {
    asm volatile(
        "mma.sync.aligned.m16n8k16.row.col.f32.bf16.bf16.f32 "
        "{%0,%1,%2,%3}, {%4,%5,%6,%7}, {%8,%9}, {%0,%1,%2,%3};"
        : "+f"(c[0]), "+f"(c[1]), "+f"(c[2]), "+f"(c[3])
        : "r"(a[0]), "r"(a[1]), "r"(a[2]), "r"(a[3]), "r"(b[0]), "r"(b[1]));
}
#define SW128(x) ((x) ^ (((x) >> 3) & 0x70))

// ---------------- TMA / mbarrier --------------------------------------------
#define MBAR_INIT(mb, c) asm volatile("mbarrier.init.shared.b64 [%0], %1;" :: "r"((uint32_t)(mb)), "r"((uint32_t)(c)) : "memory")
#define MBAR_EXPECT_TX(mb, tx) asm volatile("mbarrier.arrive.expect_tx.shared.b64 _, [%0], %1;" :: "r"((uint32_t)(mb)), "r"((uint32_t)(tx)) : "memory")
__device__ __forceinline__ void mbar_wait(uint32_t mb, uint32_t ph) {
    asm volatile(
        "{\n\t.reg .pred P1;\n\t"
        "WL_%=:\n\t"
        "mbarrier.try_wait.parity.acquire.cta.shared::cta.b64 P1, [%0], %1, 0x989680;\n\t"
        "@P1 bra.uni WD_%=;\n\t"
        "bra.uni WL_%=;\n\t"
        "WD_%=:\n\t}"
        :: "r"(mb), "r"(ph) : "memory");
}
__device__ __forceinline__ void tma2d(uint32_t dst, const void* map,
                                      int x, int y, uint32_t mbar) {
    asm volatile(
        "cp.async.bulk.tensor.2d.shared::cta.global.tile.mbarrier::complete_tx::bytes "
        "[%0], [%1, {%2, %3}], [%4];"
        :: "r"(dst), "l"(map), "r"(x), "r"(y), "r"(mbar) : "memory");
}

// ---------------- fused split fp32 -> bf16 hi/lo (all 5 tensors) ------------
// FIXED: source offset (soff) is computed independently of destination plane
// offset (doff). R8 bug: off was shifted for the dst plane BEFORE the src read,
// so wk/wv were read out of bounds -> garbage K/V weights.
__global__ __launch_bounds__(256)
void split_all(const float* __restrict__ x,  const float* __restrict__ wq,
               const float* __restrict__ wk, const float* __restrict__ wv,
               const float* __restrict__ wo)
{
    const int XN4 = MTOT * DIMC / 4;     // 786432
    const int WN4 = PER / 4;             // 147456
    int i = blockIdx.x * blockDim.x + threadIdx.x;
    const float* src;
    __nv_bfloat16 *hi, *lo;
    int soff, doff;
    if (i < XN4) {
        src = x; hi = g_xh; lo = g_xl; soff = i; doff = i;
    } else {
        int j = i - XN4;
        int r = j / WN4;
        soff = j - r * WN4;
        if (r == 0)      { src = wq; hi = g_wh;  lo = g_wl;  doff = soff; }
        else if (r == 1) { src = wk; hi = g_wh;  lo = g_wl;  doff = soff + WN4; }
        else if (r == 2) { src = wv; hi = g_wh;  lo = g_wl;  doff = soff + 2 * WN4; }
        else             { src = wo; hi = g_woh; lo = g_wol; doff = soff; }
    }
    float4 v = reinterpret_cast<const float4*>(src)[soff];
    __nv_bfloat16 h0 = __float2bfloat16(v.x), h1 = __float2bfloat16(v.y);
    __nv_bfloat16 h2 = __float2bfloat16(v.z), h3 = __float2bfloat16(v.w);
    __nv_bfloat16 l0 = __float2bfloat16(v.x - __bfloat162float(h0));
    __nv_bfloat16 l1 = __float2bfloat16(v.y - __bfloat162float(h1));
    __nv_bfloat16 l2 = __float2bfloat16(v.z - __bfloat162float(h2));
    __nv_bfloat16 l3 = __float2bfloat16(v.w - __bfloat162float(h3));
    uint2 hp, lp;
    hp.x = (uint32_t)__bfloat16_as_ushort(h0) | ((uint32_t)__bfloat16_as_ushort(h1) << 16);
    hp.y = (uint32_t)__bfloat16_as_ushort(h2) | ((uint32_t)__bfloat16_as_ushort(h3) << 16);
    lp.x = (uint32_t)__bfloat16_as_ushort(l0) | ((uint32_t)__bfloat16_as_ushort(l1) << 16);
    lp.y = (uint32_t)__bfloat16_as_ushort(l2) | ((uint32_t)__bfloat16_as_ushort(l3) << 16);
    reinterpret_cast<uint2*>(hi)[doff] = hp;
    reinterpret_cast<uint2*>(lo)[doff] = lp;
}

// ---------------- TMA-fed split-bf16 NT GEMM (unchanged, validated) ---------
#define GST   49152
#define GSA_L 16384
#define GSB_H 32768
#define GSB_L 40960
#define GEMM_DSMEM (2 * GST + 1024)

__global__ __launch_bounds__(256)
void gemm_tma(const __grid_constant__ CUtensorMap mAh,
              const __grid_constant__ CUtensorMap mAl,
              const __grid_constant__ CUtensorMap mBh,
              const __grid_constant__ CUtensorMap mBl,
              float* __restrict__ C, const float* __restrict__ bias,
              int Ncols, size_t strideC)
{
    extern __shared__ char dsm[];
    __shared__ __align__(8) uint64_t mbarrier_s[2];
    const int tid = threadIdx.x;
    const int w = tid >> 5, lane = tid & 31;
    const int wr = w >> 1, wc = w & 1;
    const int m0 = blockIdx.y * 128, n0 = blockIdx.x * 64;
    const int z = blockIdx.z;
    const int yB = z * DIMC + n0;
    C += (size_t)z * strideC;

    const uint32_t sb = (smem_u32(dsm) + 1023u) & ~1023u;
    const uint32_t mb0 = smem_u32(&mbarrier_s[0]);
    const uint32_t mb1 = smem_u32(&mbarrier_s[1]);

    if (tid == 0) { MBAR_INIT(mb0, 1); MBAR_INIT(mb1, 1); }
    __syncthreads();

    if (tid == 0) {
#pragma unroll
        for (int s = 0; s < 2; ++s) {
            uint32_t mb = s ? mb1 : mb0;
            uint32_t base = sb + s * GST;
            MBAR_EXPECT_TX(mb, GST);
            tma2d(base,          &mAh, s * 64, m0, mb);
            tma2d(base + GSA_L,  &mAl, s * 64, m0, mb);
            tma2d(base + GSB_H,  &mBh, s * 64, yB, mb);
            tma2d(base + GSB_L,  &mBl, s * 64, yB, mb);
        }
    }

    float acc[2][4][4];
#pragma unroll
    for (int i = 0; i < 2; i++)
#pragma unroll
        for (int j = 0; j < 4; j++)
#pragma unroll
            for (int t = 0; t < 4; t++) acc[i][j][t] = 0.f;

    const int rA = lane & 15;
    const int cA = (lane >> 4) * 8;
    const int rB = ((lane >> 4) & 1) * 8 + (lane & 7);
    const int cB = ((lane >> 3) & 1) * 8;
    const int NCH = KDIM / 64;

    for (int c = 0; c < NCH; ++c) {
        const int b = c & 1;
        mbar_wait(b ? mb1 : mb0, (c >> 1) & 1);
        const uint32_t base = sb + b * GST;
#pragma unroll
        for (int ks = 0; ks < 4; ++ks) {
            uint32_t aH[2][4], aL[2][4], bH[4][2], bL[4][2];
#pragma unroll
            for (int mi = 0; mi < 2; ++mi) {
                uint32_t off = (uint32_t)((wr * 32 + mi * 16 + rA) * 128
                             + (ks * 16 + cA) * 2);
                uint32_t sw = SW128(off);
                ldsm4(aH[mi], base + sw);
                ldsm4(aL[mi], base + GSA_L + sw);
            }
#pragma unroll
            for (int njj = 0; njj < 2; ++njj) {
                uint32_t off = (uint32_t)((wc * 32 + njj * 16 + rB) * 128
                             + (ks * 16 + cB) * 2);
                uint32_t sw = SW128(off);
                uint32_t r[4];
                ldsm4(r, base + GSB_H + sw);
                bH[njj * 2][0] = r[0]; bH[njj * 2][1] = r[1];
                bH[njj * 2 + 1][0] = r[2]; bH[njj * 2 + 1][1] = r[3];
                ldsm4(r, base + GSB_L + sw);
                bL[njj * 2][0] = r[0]; bL[njj * 2][1] = r[1];
                bL[njj * 2 + 1][0] = r[2]; bL[njj * 2 + 1][1] = r[3];
            }
#pragma unroll
            for (int mi = 0; mi < 2; ++mi)
#pragma unroll
                for (int nj = 0; nj < 4; ++nj) {
                    mma16816(acc[mi][nj], aH[mi], bH[nj]);
                    mma16816(acc[mi][nj], aH[mi], bL[nj]);
                    mma16816(acc[mi][nj], aL[mi], bH[nj]);
                }
        }
        __syncthreads();
        if (c + 2 < NCH && tid == 0) {
            uint32_t mb = b ? mb1 : mb0;
            uint32_t base2 = sb + b * GST;
            MBAR_EXPECT_TX(mb, GST);
            tma2d(base2,         &mAh, (c + 2) * 64, m0, mb);
            tma2d(base2 + GSA_L, &mAl, (c + 2) * 64, m0, mb);
            tma2d(base2 + GSB_H, &mBh, (c + 2) * 64, yB, mb);
            tma2d(base2 + GSB_L, &mBl, (c + 2) * 64, yB, mb);
        }
    }

#pragma unroll
    for (int mi = 0; mi < 2; ++mi) {
        int gr = m0 + wr * 32 + mi * 16 + (lane >> 2);
#pragma unroll
        for (int nj = 0; nj < 4; ++nj) {
            int gc = n0 + wc * 32 + nj * 8 + (lane & 3) * 2;
            float2 v0, v1;
            v0.x = acc[mi][nj][0]; v0.y = acc[mi][nj][1];
            v1.x = acc[mi][nj][2]; v1.y = acc[mi][nj][3];
            if (bias) {
                float b0 = bias[gc], b1 = bias[gc + 1];
                v0.x += b0; v0.y += b1; v1.x += b0; v1.y += b1;
            }
            *reinterpret_cast<float2*>(C + (size_t)gr * Ncols + gc) = v0;
            *reinterpret_cast<float2*>(C + (size_t)(gr + 8) * Ncols + gc) = v1;
        }
    }
}

// ---------------- SPD log-projection -> scaled bf16 hi/lo + scaled norm -----
__global__ __launch_bounds__(256)
void lproj2(const float* __restrict__ src, const float* __restrict__ w,
            const float* __restrict__ bias, __nv_bfloat16* __restrict__ lp,
            float* __restrict__ l2arr)
{
    __shared__ float s_w[RK][HD];
    __shared__ float s_b[RK];
    __shared__ float s_q[128][HD + 1];

    const int bid  = blockIdx.x;
    const int bh   = bid >> 3;
    const int tile = bid & 7;
    const int b    = bh / NH;
    const int h    = bh - b * NH;
    const int tid  = threadIdx.x;

    ((float*)s_w)[tid]       = w[tid & 511];
    ((float*)s_w)[tid + 256] = w[(tid + 256) & 511];
    if (tid < RK) s_b[tid] = bias[tid];

    const float* base = src + ((size_t)(b * SEQ) + tile * 128) * DIMC + h * HD;
#pragma unroll
    for (int u = 0; u < 8; ++u) {
        int s   = tid + u * 256;
        int row = s >> 4;
        int c4  = (s & 15) << 2;
        float4 v = *reinterpret_cast<const float4*>(base + (size_t)row * DIMC + c4);
        s_q[row][c4 + 0] = v.x; s_q[row][c4 + 1] = v.y;
        s_q[row][c4 + 2] = v.z; s_q[row][c4 + 3] = v.w;
    }
    __syncthreads();

    const int token = tid >> 1;
    const int r0    = (tid & 1) * 4;
    float z0 = s_b[r0 + 0], z1 = s_b[r0 + 1], z2 = s_b[r0 + 2], z3 = s_b[r0 + 3];
#pragma unroll
    for (int d = 0; d < HD; ++d) {
        float q = s_q[token][d];
        z0 = fmaf(q, s_w[r0 + 0][d], z0);
        z1 = fmaf(q, s_w[r0 + 1][d], z1);
        z2 = fmaf(q, s_w[r0 + 2][d], z2);
        z3 = fmaf(q, s_w[r0 + 3][d], z3);
    }
    float zz[4] = {z0, z1, z2, z3};
    float hi4[4], lo4[4];
    float s2 = 0.f;
#pragma unroll
    for (int i = 0; i < 4; ++i) {
        float z = zz[i];
        float sp = (z > 20.f) ? z : log1pf(expf(z));
        float l = 0.125f * logf(sp + 1e-6f + 1e-8f);   // scaled by SCALE
        s2 = fmaf(l, l, s2);
        float h = __bfloat162float(__float2bfloat16(l));
        hi4[i] = h;
        lo4[i] = l - h;
    }
    s2 += __shfl_xor_sync(0xffffffffu, s2, 1);

    const size_t t = (size_t)bh * SEQ + tile * 128 + token;
    uint2 hp, lq;
    hp.x = pack_bf16x2(hi4[0], hi4[1]);
    hp.y = pack_bf16x2(hi4[2], hi4[3]);
    lq.x = pack_bf16x2(lo4[0], lo4[1]);
    lq.y = pack_bf16x2(lo4[2], lo4[3]);
    *reinterpret_cast<uint2*>(lp + t * 16 + r0)     = hp;
    *reinterpret_cast<uint2*>(lp + t * 16 + 8 + r0) = lq;
    if ((tid & 1) == 0) l2arr[t] = s2;
}

// ---------------- SV precompute ---------------------------------------------
__global__ __launch_bounds__(256)
void svsum_kernel()
{
    __shared__ float part[4][HD];
    const int bh = blockIdx.x;
    const int b = bh / NH, h = bh - b * NH;
    const int tid = threadIdx.x;
    const int d = tid & 63, seg = tid >> 6;
    const float* Vp = g_qkv + (size_t)2 * MTOT * DIMC
                    + (size_t)(b * SEQ) * DIMC + h * HD + d;
    float s = 0.f;
    for (int k = seg * 256; k < seg * 256 + 256; ++k)
        s += Vp[(size_t)k * DIMC];
    part[seg][d] = s;
    __syncthreads();
    if (tid < HD)
        g_sv[bh * HD + tid] = part[0][tid] + part[1][tid]
                            + part[2][tid] + part[3][tid];
}

// ---------------- geodesic attention: S on tensor cores, u in registers -----
#define AKT 64
#define UP  72
#define LQP 24

__global__ __launch_bounds__(256, 2)
void attn_mma()
{
    __shared__ __align__(16) __nv_bfloat16 s_lq [128][LQP];
    __shared__ __align__(16) __nv_bfloat16 s_lkA[AKT][LQP];
    __shared__ __align__(16) __nv_bfloat16 s_lkB[AKT][LQP];
    __shared__ float s_lk2[AKT];
    __shared__ float s_sv[HD];
    __shared__ float s_linv[128];
    __shared__ __align__(16) __nv_bfloat16 s_v[AKT][UP];

    const int qb = blockIdx.x, bh = blockIdx.y;
    const int b = bh / NH, h = bh - b * NH;
    const int tid = threadIdx.x, lane = tid & 31, w = tid >> 5;
    const int qq = lane >> 2, ii = lane & 3;
    const int rowq = 16 * w + qq;

    {
        int row = tid >> 1, half = tid & 1;
        *reinterpret_cast<uint4*>(&s_lq[row][half * 8]) =
            *reinterpret_cast<const uint4*>(
                g_lqp + ((size_t)bh * SEQ + qb * 128 + row) * 16 + half * 8);
    }
    if (tid < HD) s_sv[tid] = g_sv[bh * HD + tid];
    const float lq2_0 = g_lq2[(size_t)bh * SEQ + qb * 128 + rowq];
    const float lq2_1 = g_lq2[(size_t)bh * SEQ + qb * 128 + rowq + 8];
    __syncthreads();

    uint32_t aF[4];
    ldsm4(aF, smem_u32(&s_lq[16 * w + (lane & 15)][(lane >> 4) * 8]));

    const float* Vp  = g_qkv + (size_t)2 * MTOT * DIMC
                     + (size_t)(b * SEQ) * DIMC + h * HD;
    const __nv_bfloat16* Lkp = g_lkp + (size_t)bh * SEQ * 16;
    const float* Lk2 = g_lk2 + (size_t)bh * SEQ;

    float acc[8][4];
#pragma unroll
    for (int i = 0; i < 8; i++)
#pragma unroll
        for (int j = 0; j < 4; j++) acc[i][j] = 0.f;
    float us0 = 0.f, us1 = 0.f;

    const int rB = ((lane >> 4) & 1) * 8 + (lane & 7);
    const int cB = ((lane >> 3) & 1) * 8;
    const int rL = lane & 15, cL = (lane >> 4) * 8;

    for (int kt = 0; kt < SEQ / AKT; ++kt) {
        const int key0 = kt * AKT;
        __syncthreads();
        if (tid < 64) {              // lk hi -> [hi|hi]
            uint4 hv = *reinterpret_cast<const uint4*>(Lkp + (key0 + tid) * 16);
            *reinterpret_cast<uint4*>(&s_lkA[tid][0]) = hv;
            *reinterpret_cast<uint4*>(&s_lkA[tid][8]) = hv;
        } else if (tid < 128) {      // lk lo -> [lo|0]
            int r = tid - 64;
            uint4 lv = *reinterpret_cast<const uint4*>(Lkp + (key0 + r) * 16 + 8);
            *reinterpret_cast<uint4*>(&s_lkB[r][0]) = lv;
            *reinterpret_cast<uint4*>(&s_lkB[r][8]) = make_uint4(0, 0, 0, 0);
        } else if (tid < 192) {
            s_lk2[tid - 128] = Lk2[key0 + tid - 128];
        }
#pragma unroll
        for (int u2 = 0; u2 < 4; ++u2) {
            int s = tid + u2 * 256;
            int key = s >> 4, d4 = (s & 15) * 4;
            float4 v = *(const float4*)(Vp + (size_t)(key0 + key) * DIMC + d4);
            uint2 pk;
            pk.x = pack_bf16x2(v.x, v.y);
            pk.y = pack_bf16x2(v.z, v.w);
            *reinterpret_cast<uint2*>(&s_v[key][d4]) = pk;
        }
        __syncthreads();

        uint32_t uA[4][4];
#pragma unroll
        for (int hhalf = 0; hhalf < 2; ++hhalf) {
            float sacc[4][4];
#pragma unroll
            for (int i = 0; i < 4; i++)
#pragma unroll
                for (int j = 0; j < 4; j++) sacc[i][j] = 0.f;
#pragma unroll
            for (int nj = 0; nj < 2; ++nj) {
                int njj = 2 * hhalf + nj;
                uint32_t addr = (njj * 16 + rB) * (LQP * 2) + cB * 2;
                uint32_t r[4];
                ldsm4(r, smem_u32(s_lkA) + addr);
                uint32_t bb0[2] = {r[0], r[1]};
                uint32_t bb1[2] = {r[2], r[3]};
                uint32_t r2[4];
                ldsm4(r2, smem_u32(s_lkB) + addr);
                uint32_t bc0[2] = {r2[0], r2[1]};
                uint32_t bc1[2] = {r2[2], r2[3]};
                mma16816(sacc[2 * nj],     aF, bb0);
                mma16816(sacc[2 * nj],     aF, bc0);
                mma16816(sacc[2 * nj + 1], aF, bb1);
                mma16816(sacc[2 * nj + 1], aF, bc1);
            }
#pragma unroll
            for (int k = 0; k < 4; ++k) {
                int nc = 4 * hhalf + k;
                int col = 8 * nc + 2 * ii;
                float lk0 = s_lk2[col], lk1 = s_lk2[col + 1];
                float d00 = fmaf(-2.f, sacc[k][0], lq2_0 + lk0);
                float d01 = fmaf(-2.f, sacc[k][1], lq2_0 + lk1);
                float d10 = fmaf(-2.f, sacc[k][2], lq2_1 + lk0);
                float d11 = fmaf(-2.f, sacc[k][3], lq2_1 + lk1);
                d00 = fmaxf(d00, 1.5625e-14f);
                d01 = fmaxf(d01, 1.5625e-14f);
                d10 = fmaxf(d10, 1.5625e-14f);
                d11 = fmaxf(d11, 1.5625e-14f);
                float t00 = sqa(d00), t01 = sqa(d01);
                float t10 = sqa(d10), t11 = sqa(d11);
                const float c2 = -0.5f, c3 = 0.16666667f, c4 = -0.041666667f;
                float u00 = t00 * fmaf(t00, fmaf(t00, fmaf(t00, c4, c3), c2), 1.f);
                float u01 = t01 * fmaf(t01, fmaf(t01, fmaf(t01, c4, c3), c2), 1.f);
                float u10 = t10 * fmaf(t10, fmaf(t10, fmaf(t10, c4, c3), c2), 1.f);
                float u11 = t11 * fmaf(t11, fmaf(t11, fmaf(t11, c4, c3), c2), 1.f);
                us0 += u00 + u01;
                us1 += u10 + u11;
                int kc = nc >> 1;
                if ((nc & 1) == 0) {
                    uA[kc][0] = pack_bf16x2(u00, u01);
                    uA[kc][1] = pack_bf16x2(u10, u11);
                } else {
                    uA[kc][2] = pack_bf16x2(u00, u01);
                    uA[kc][3] = pack_bf16x2(u10, u11);
                }
            }
        }

#pragma unroll
        for (int kc = 0; kc < 4; ++kc) {
#pragma unroll
            for (int vc = 0; vc < 4; ++vc) {
                uint32_t r[4];
                ldsm4t(r, smem_u32(&s_v[16 * kc + rL][16 * vc + cL]));
                mma16816(acc[2 * vc],     uA[kc], r);
                mma16816(acc[2 * vc + 1], uA[kc], r + 2);
            }
        }
    }

    us0 += __shfl_xor_sync(0xffffffffu, us0, 1);
    us0 += __shfl_xor_sync(0xffffffffu, us0, 2);
    us1 += __shfl_xor_sync(0xffffffffu, us1, 1);
    us1 += __shfl_xor_sync(0xffffffffu, us1, 2);
    if (ii == 0) {
        s_linv[rowq]     = 1.f / (1024.f - us0);
        s_linv[rowq + 8] = 1.f / (1024.f - us1);
    }
    __syncthreads();

    const float ilo = s_linv[rowq], ihi = s_linv[rowq + 8];
    const size_t rowb = (size_t)(b * SEQ + qb * 128) * DIMC + h * HD;
#pragma unroll
    for (int nc = 0; nc < 8; ++nc) {
        int c = 8 * nc + ii * 2;
        float sv0 = s_sv[c], sv1 = s_sv[c + 1];
        float o00 = (sv0 - acc[nc][0]) * ilo;
        float o01 = (sv1 - acc[nc][1]) * ilo;
        float o10 = (sv0 - acc[nc][2]) * ihi;
        float o11 = (sv1 - acc[nc][3]) * ihi;
        float h00 = __bfloat162float(__float2bfloat16(o00));
        float h01 = __bfloat162float(__float2bfloat16(o01));
        float h10 = __bfloat162float(__float2bfloat16(o10));
        float h11 = __bfloat162float(__float2bfloat16(o11));
        size_t a0 = rowb + (size_t)rowq * DIMC + c;
        size_t a1 = rowb + (size_t)(rowq + 8) * DIMC + c;
        *reinterpret_cast<uint32_t*>(g_ch + a0) = pack_bf16x2(h00, h01);
        *reinterpret_cast<uint32_t*>(g_cl + a0) = pack_bf16x2(o00 - h00, o01 - h01);
        *reinterpret_cast<uint32_t*>(g_ch + a1) = pack_bf16x2(h10, h11);
        *reinterpret_cast<uint32_t*>(g_cl + a1) = pack_bf16x2(o10 - h10, o11 - h11);
    }
}

// ---------------- KL term (vectorized deterministic reduction) --------------
__global__ __launch_bounds__(256)
void kl_partial(const float* __restrict__ m0, const float* __restrict__ l0,
                const float* __restrict__ m1, const float* __restrict__ l1,
                const float* __restrict__ m2, const float* __restrict__ l2,
                const float* __restrict__ m3, const float* __restrict__ l3)
{
    const int PER4 = PER / 4;
    const int TOT4 = 4 * PER4;
    const float L2E2 = 2.0f * 1.4426950408889634f;
    float s = 0.f;
    for (int i4 = blockIdx.x * blockDim.x + threadIdx.x; i4 < TOT4;
         i4 += gridDim.x * blockDim.x) {
        int p   = i4 / PER4;
        int off = i4 - p * PER4;
        const float* mp = (p == 0) ? m0 : (p == 1) ? m1 : (p == 2) ? m2 : m3;
        const float* lp = (p == 0) ? l0 : (p == 1) ? l1 : (p == 2) ? l2 : l3;
        float4 mu = reinterpret_cast<const float4*>(mp)[off];
        float4 ls = reinterpret_cast<const float4*>(lp)[off];
        s += 0.5f * (ex2a(L2E2 * ls.x) + mu.x * mu.x - 1.f - 2.f * ls.x);
        s += 0.5f * (ex2a(L2E2 * ls.y) + mu.y * mu.y - 1.f - 2.f * ls.y);
        s += 0.5f * (ex2a(L2E2 * ls.z) + mu.z * mu.z - 1.f - 2.f * ls.z);
        s += 0.5f * (ex2a(L2E2 * ls.w) + mu.w * mu.w - 1.f - 2.f * ls.w);
    }
    __shared__ float red[256];
    red[threadIdx.x] = s;
    __syncthreads();
    for (int w = 128; w > 0; w >>= 1) {
        if (threadIdx.x < w) red[threadIdx.x] += red[threadIdx.x + w];
        __syncthreads();
    }
    if (threadIdx.x == 0) g_klpart[blockIdx.x] = red[0];
}

__global__ void kl_final(float* __restrict__ dst)
{
    __shared__ float red[256];
    red[threadIdx.x] = g_klpart[threadIdx.x];
    __syncthreads();
    for (int w = 128; w > 0; w >>= 1) {
        if (threadIdx.x < w) red[threadIdx.x] += red[threadIdx.x + w];
        __syncthreads();
    }
    if (threadIdx.x == 0) *dst = red[0];
}

// ---------------- host: tensor map encoding ---------------------------------
typedef CUresult (*PFN_tmEnc)(CUtensorMap*, CUtensorMapDataType, cuuint32_t,
                              void*, const cuuint64_t*, const cuuint64_t*,
                              const cuuint32_t*, const cuuint32_t*,
                              CUtensorMapInterleave, CUtensorMapSwizzle,
                              CUtensorMapL2promotion, CUtensorMapFloatOOBfill);

static void encode_map(PFN_tmEnc fn, CUtensorMap* m, void* ptr,
                       unsigned long long rows, unsigned boxRows)
{
    cuuint64_t dims[2]    = {(cuuint64_t)KDIM, (cuuint64_t)rows};
    cuuint64_t strides[1] = {(cuuint64_t)KDIM * 2};
    cuuint32_t box[2]     = {64u, boxRows};
    cuuint32_t es[2]      = {1u, 1u};
    fn(m, CU_TENSOR_MAP_DATA_TYPE_BFLOAT16, 2, ptr, dims, strides, box, es,
       CU_TENSOR_MAP_INTERLEAVE_NONE, CU_TENSOR_MAP_SWIZZLE_128B,
       CU_TENSOR_MAP_L2_PROMOTION_L2_128B, CU_TENSOR_MAP_FLOAT_OOB_FILL_NONE);
}

// ---------------- launcher -------------------------------------------------
extern "C" void kernel_launch(void* const* d_in, const int* in_sizes, int n_in,
                              void* d_out, int out_size)
{
    const float* x     = (const float*)d_in[0];
    const float* wq_mu = (const float*)d_in[1];
    const float* wq_ls = (const float*)d_in[2];
    const float* wk_mu = (const float*)d_in[3];
    const float* wk_ls = (const float*)d_in[4];
    const float* wv_mu = (const float*)d_in[5];
    const float* wv_ls = (const float*)d_in[6];
    const float* wo_mu = (const float*)d_in[7];
    const float* wo_ls = (const float*)d_in[8];
    const float* wo_b  = (const float*)d_in[9];
    const float* sq_w  = (const float*)d_in[10];
    const float* sq_b  = (const float*)d_in[11];
    const float* sk_w  = (const float*)d_in[12];
    const float* sk_b  = (const float*)d_in[13];
    float* out = (float*)d_out;

    float *qkv_d, *lq2_d, *lk2_d;
    __nv_bfloat16 *lqp_d, *lkp_d;
    __nv_bfloat16 *xh_d, *xl_d, *wh_d, *wl_d, *woh_d, *wol_d, *ch_d, *cl_d;
    cudaGetSymbolAddress((void**)&qkv_d, g_qkv);
    cudaGetSymbolAddress((void**)&lqp_d, g_lqp);
    cudaGetSymbolAddress((void**)&lkp_d, g_lkp);
    cudaGetSymbolAddress((void**)&lq2_d, g_lq2);
    cudaGetSymbolAddress((void**)&lk2_d, g_lk2);
    cudaGetSymbolAddress((void**)&xh_d,  g_xh);
    cudaGetSymbolAddress((void**)&xl_d,  g_xl);
    cudaGetSymbolAddress((void**)&wh_d,  g_wh);
    cudaGetSymbolAddress((void**)&wl_d,  g_wl);
    cudaGetSymbolAddress((void**)&woh_d, g_woh);
    cudaGetSymbolAddress((void**)&wol_d, g_wol);
    cudaGetSymbolAddress((void**)&ch_d,  g_ch);
    cudaGetSymbolAddress((void**)&cl_d,  g_cl);

    static PFN_tmEnc tmEnc = nullptr;
    if (!tmEnc) {
        cudaDriverEntryPointQueryResult qr;
        cudaGetDriverEntryPoint("cuTensorMapEncodeTiled", (void**)&tmEnc,
                                cudaEnableDefault, &qr);
    }
    CUtensorMap mXh, mXl, mWh, mWl, mCh, mCl, mOh, mOl;
    encode_map(tmEnc, &mXh, xh_d,  MTOT,     128);
    encode_map(tmEnc, &mXl, xl_d,  MTOT,     128);
    encode_map(tmEnc, &mWh, wh_d,  3 * DIMC, 64);
    encode_map(tmEnc, &mWl, wl_d,  3 * DIMC, 64);
    encode_map(tmEnc, &mCh, ch_d,  MTOT,     128);
    encode_map(tmEnc, &mCl, cl_d,  MTOT,     128);
    encode_map(tmEnc, &mOh, woh_d, DIMC,     64);
    encode_map(tmEnc, &mOl, wol_d, DIMC,     64);

    cudaFuncSetAttribute(gemm_tma, cudaFuncAttributeMaxDynamicSharedMemorySize,
                         GEMM_DSMEM);

    const int TOTAL4 = MTOT * DIMC / 4 + 4 * (PER / 4);   // 1376256
    split_all<<<TOTAL4 / 256, 256>>>(x, wq_mu, wk_mu, wv_mu, wo_mu);

    gemm_tma<<<dim3(DIMC / 64, MTOT / 128, 3), 256, GEMM_DSMEM>>>(
        mXh, mXl, mWh, mWl, qkv_d, nullptr, DIMC, (size_t)MTOT * DIMC);

    lproj2<<<BH * 8, 256>>>(qkv_d + 0 * (size_t)MTOT * DIMC, sq_w, sq_b, lqp_d, lq2_d);
    lproj2<<<BH * 8, 256>>>(qkv_d + 1 * (size_t)MTOT * DIMC, sk_w, sk_b, lkp_d, lk2_d);
    svsum_kernel<<<BH, 256>>>();

    attn_mma<<<dim3(SEQ / 128, BH), 256>>>();

    gemm_tma<<<dim3(DIMC / 64, MTOT / 128, 1), 256, GEMM_DSMEM>>>(
        mCh, mCl, mOh, mOl, out, wo_b, DIMC, 0);

    kl_partial<<<256, 256>>>(wq_mu, wq_ls, wk_mu, wk_ls,
                             wv_mu, wv_ls, wo_mu, wo_ls);
    if (out_size > MTOT * DIMC) {
        kl_final<<<1, 256>>>(out + (size_t)out_size - 1);
    }
}

// round 10
// speedup vs baseline: 4.6269x; 1.0496x over previous
#include <cuda_runtime.h>
#include <cuda.h>
#include <cuda_bf16.h>
#include <cstdint>
#include <math.h>

#define BATCH 4
#define SEQ   1024
#define DIMC  768
#define NH    12
#define HD    64
#define RK    8
#define MTOT  (BATCH*SEQ)     /* 4096 */
#define BH    (BATCH*NH)      /* 48   */
#define KDIM  768
#define PER   (DIMC*DIMC)

// ---------------- scratch (device globals; no allocation allowed) ----------
__device__ __align__(16) float g_qkv[3*MTOT*DIMC];     // q,k,v planes
__device__ __align__(16) __nv_bfloat16 g_lqp[BH*SEQ*16]; // [hi8|lo8] scaled
__device__ __align__(16) __nv_bfloat16 g_lkp[BH*SEQ*16];
__device__ __align__(16) float g_lq2[BH*SEQ];            // scaled |lq'|^2
__device__ __align__(16) float g_lk2[BH*SEQ];
__device__ __align__(16) float g_sv [BH*HD];
__device__ float g_klpart[256];
__device__ __align__(1024) __nv_bfloat16 g_xh [MTOT*DIMC];
__device__ __align__(1024) __nv_bfloat16 g_xl [MTOT*DIMC];
__device__ __align__(1024) __nv_bfloat16 g_wh [3*PER];
__device__ __align__(1024) __nv_bfloat16 g_wl [3*PER];
__device__ __align__(1024) __nv_bfloat16 g_woh[PER];
__device__ __align__(1024) __nv_bfloat16 g_wol[PER];
__device__ __align__(1024) __nv_bfloat16 g_ch [MTOT*DIMC];
__device__ __align__(1024) __nv_bfloat16 g_cl [MTOT*DIMC];

// ---------------- fast approx helpers --------------------------------------
__device__ __forceinline__ float ex2a(float x) {
    float y; asm("ex2.approx.f32 %0, %1;" : "=f"(y) : "f"(x)); return y;
}
__device__ __forceinline__ float sqa(float x) {
    float y; asm("sqrt.approx.f32 %0, %1;" : "=f"(y) : "f"(x)); return y;
}
__device__ __forceinline__ uint32_t pack_bf16x2(float lo, float hi) {
    uint32_t r;
    asm("cvt.rn.bf16x2.f32 %0, %1, %2;" : "=r"(r) : "f"(hi), "f"(lo));
    return r;
}

// ---------------- smem / mma primitives -------------------------------------
__device__ __forceinline__ uint32_t smem_u32(const void* p) {
    uint32_t a;
    asm("{ .reg .u64 t; cvta.to.shared.u64 t, %1; cvt.u32.u64 %0, t; }"
        : "=r"(a) : "l"(p));
    return a;
}
__device__ __forceinline__ void ldsm4(uint32_t* r, uint32_t addr) {
    asm volatile("ldmatrix.sync.aligned.m8n8.x4.shared.b16 {%0,%1,%2,%3}, [%4];"
        : "=r"(r[0]), "=r"(r[1]), "=r"(r[2]), "=r"(r[3]) : "r"(addr));
}
__device__ __forceinline__ void ldsm4t(uint32_t* r, uint32_t addr) {
    asm volatile("ldmatrix.sync.aligned.m8n8.x4.trans.shared.b16 {%0,%1,%2,%3}, [%4];"
        : "=r"(r[0]), "=r"(r[1]), "=r"(r[2]), "=r"(r[3]) : "r"(addr));
}
__device__ __forceinline__ void mma16816(float* c, const uint32_t* a,
                                         const uint32_t* b) {
    asm volatile(
        "mma.sync.aligned.m16n8k16.row.col.f32.bf16.bf16.f32 "
        "{%0,%1,%2,%3}, {%4,%5,%6,%7}, {%8,%9}, {%0,%1,%2,%3};"
        : "+f"(c[0]), "+f"(c[1]), "+f"(c[2]), "+f"(c[3])
        : "r"(a[0]), "r"(a[1]), "r"(a[2]), "r"(a[3]), "r"(b[0]), "r"(b[1]));
}
#define SW128(x) ((x) ^ (((x) >> 3) & 0x70))

// ---------------- TMA / mbarrier --------------------------------------------
#define MBAR_INIT(mb, c) asm volatile("mbarrier.init.shared.b64 [%0], %1;" :: "r"((uint32_t)(mb)), "r"((uint32_t)(c)) : "memory")
#define MBAR_EXPECT_TX(mb, tx) asm volatile("mbarrier.arrive.expect_tx.shared.b64 _, [%0], %1;" :: "r"((uint32_t)(mb)), "r"((uint32_t)(tx)) : "memory")
__device__ __forceinline__ void mbar_wait(uint32_t mb, uint32_t ph) {
    asm volatile(
        "{\n\t.reg .pred P1;\n\t"
        "WL_%=:\n\t"
        "mbarrier.try_wait.parity.acquire.cta.shared::cta.b64 P1, [%0], %1, 0x989680;\n\t"
        "@P1 bra.uni WD_%=;\n\t"
        "bra.uni WL_%=;\n\t"
        "WD_%=:\n\t}"
        :: "r"(mb), "r"(ph) : "memory");
}
__device__ __forceinline__ void tma2d(uint32_t dst, const void* map,
                                      int x, int y, uint32_t mbar) {
    asm volatile(
        "cp.async.bulk.tensor.2d.shared::cta.global.tile.mbarrier::complete_tx::bytes "
        "[%0], [%1, {%2, %3}], [%4];"
        :: "r"(dst), "l"(map), "r"(x), "r"(y), "r"(mbar) : "memory");
}

// ---------------- fused split fp32 -> bf16 hi/lo (all 5 tensors) ------------
__global__ __launch_bounds__(256)
void split_all(const float* __restrict__ x,  const float* __restrict__ wq,
               const float* __restrict__ wk, const float* __restrict__ wv,
               const float* __restrict__ wo)
{
    const int XN4 = MTOT * DIMC / 4;     // 786432
    const int WN4 = PER / 4;             // 147456
    int i = blockIdx.x * blockDim.x + threadIdx.x;
    const float* src;
    __nv_bfloat16 *hi, *lo;
    int soff, doff;
    if (i < XN4) {
        src = x; hi = g_xh; lo = g_xl; soff = i; doff = i;
    } else {
        int j = i - XN4;
        int r = j / WN4;
        soff = j - r * WN4;
        if (r == 0)      { src = wq; hi = g_wh;  lo = g_wl;  doff = soff; }
        else if (r == 1) { src = wk; hi = g_wh;  lo = g_wl;  doff = soff + WN4; }
        else if (r == 2) { src = wv; hi = g_wh;  lo = g_wl;  doff = soff + 2 * WN4; }
        else             { src = wo; hi = g_woh; lo = g_wol; doff = soff; }
    }
    float4 v = reinterpret_cast<const float4*>(src)[soff];
    __nv_bfloat16 h0 = __float2bfloat16(v.x), h1 = __float2bfloat16(v.y);
    __nv_bfloat16 h2 = __float2bfloat16(v.z), h3 = __float2bfloat16(v.w);
    __nv_bfloat16 l0 = __float2bfloat16(v.x - __bfloat162float(h0));
    __nv_bfloat16 l1 = __float2bfloat16(v.y - __bfloat162float(h1));
    __nv_bfloat16 l2 = __float2bfloat16(v.z - __bfloat162float(h2));
    __nv_bfloat16 l3 = __float2bfloat16(v.w - __bfloat162float(h3));
    uint2 hp, lp;
    hp.x = (uint32_t)__bfloat16_as_ushort(h0) | ((uint32_t)__bfloat16_as_ushort(h1) << 16);
    hp.y = (uint32_t)__bfloat16_as_ushort(h2) | ((uint32_t)__bfloat16_as_ushort(h3) << 16);
    lp.x = (uint32_t)__bfloat16_as_ushort(l0) | ((uint32_t)__bfloat16_as_ushort(l1) << 16);
    lp.y = (uint32_t)__bfloat16_as_ushort(l2) | ((uint32_t)__bfloat16_as_ushort(l3) << 16);
    reinterpret_cast<uint2*>(hi)[doff] = hp;
    reinterpret_cast<uint2*>(lo)[doff] = lp;
}

// ---------------- TMA-fed split-bf16 NT GEMM (unchanged, validated) ---------
#define GST   49152
#define GSA_L 16384
#define GSB_H 32768
#define GSB_L 40960
#define GEMM_DSMEM (2 * GST + 1024)

__global__ __launch_bounds__(256)
void gemm_tma(const __grid_constant__ CUtensorMap mAh,
              const __grid_constant__ CUtensorMap mAl,
              const __grid_constant__ CUtensorMap mBh,
              const __grid_constant__ CUtensorMap mBl,
              float* __restrict__ C, const float* __restrict__ bias,
              int Ncols, size_t strideC)
{
    extern __shared__ char dsm[];
    __shared__ __align__(8) uint64_t mbarrier_s[2];
    const int tid = threadIdx.x;
    const int w = tid >> 5, lane = tid & 31;
    const int wr = w >> 1, wc = w & 1;
    const int m0 = blockIdx.y * 128, n0 = blockIdx.x * 64;
    const int z = blockIdx.z;
    const int yB = z * DIMC + n0;
    C += (size_t)z * strideC;

    const uint32_t sb = (smem_u32(dsm) + 1023u) & ~1023u;
    const uint32_t mb0 = smem_u32(&mbarrier_s[0]);
    const uint32_t mb1 = smem_u32(&mbarrier_s[1]);

    if (tid == 0) { MBAR_INIT(mb0, 1); MBAR_INIT(mb1, 1); }
    __syncthreads();

    if (tid == 0) {
#pragma unroll
        for (int s = 0; s < 2; ++s) {
            uint32_t mb = s ? mb1 : mb0;
            uint32_t base = sb + s * GST;
            MBAR_EXPECT_TX(mb, GST);
            tma2d(base,          &mAh, s * 64, m0, mb);
            tma2d(base + GSA_L,  &mAl, s * 64, m0, mb);
            tma2d(base + GSB_H,  &mBh, s * 64, yB, mb);
            tma2d(base + GSB_L,  &mBl, s * 64, yB, mb);
        }
    }

    float acc[2][4][4];
#pragma unroll
    for (int i = 0; i < 2; i++)
#pragma unroll
        for (int j = 0; j < 4; j++)
#pragma unroll
            for (int t = 0; t < 4; t++) acc[i][j][t] = 0.f;

    const int rA = lane & 15;
    const int cA = (lane >> 4) * 8;
    const int rB = ((lane >> 4) & 1) * 8 + (lane & 7);
    const int cB = ((lane >> 3) & 1) * 8;
    const int NCH = KDIM / 64;

    for (int c = 0; c < NCH; ++c) {
        const int b = c & 1;
        mbar_wait(b ? mb1 : mb0, (c >> 1) & 1);
        const uint32_t base = sb + b * GST;
#pragma unroll
        for (int ks = 0; ks < 4; ++ks) {
            uint32_t aH[2][4], aL[2][4], bH[4][2], bL[4][2];
#pragma unroll
            for (int mi = 0; mi < 2; ++mi) {
                uint32_t off = (uint32_t)((wr * 32 + mi * 16 + rA) * 128
                             + (ks * 16 + cA) * 2);
                uint32_t sw = SW128(off);
                ldsm4(aH[mi], base + sw);
                ldsm4(aL[mi], base + GSA_L + sw);
            }
#pragma unroll
            for (int njj = 0; njj < 2; ++njj) {
                uint32_t off = (uint32_t)((wc * 32 + njj * 16 + rB) * 128
                             + (ks * 16 + cB) * 2);
                uint32_t sw = SW128(off);
                uint32_t r[4];
                ldsm4(r, base + GSB_H + sw);
                bH[njj * 2][0] = r[0]; bH[njj * 2][1] = r[1];
                bH[njj * 2 + 1][0] = r[2]; bH[njj * 2 + 1][1] = r[3];
                ldsm4(r, base + GSB_L + sw);
                bL[njj * 2][0] = r[0]; bL[njj * 2][1] = r[1];
                bL[njj * 2 + 1][0] = r[2]; bL[njj * 2 + 1][1] = r[3];
            }
#pragma unroll
            for (int mi = 0; mi < 2; ++mi)
#pragma unroll
                for (int nj = 0; nj < 4; ++nj) {
                    mma16816(acc[mi][nj], aH[mi], bH[nj]);
                    mma16816(acc[mi][nj], aH[mi], bL[nj]);
                    mma16816(acc[mi][nj], aL[mi], bH[nj]);
                }
        }
        __syncthreads();
        if (c + 2 < NCH && tid == 0) {
            uint32_t mb = b ? mb1 : mb0;
            uint32_t base2 = sb + b * GST;
            MBAR_EXPECT_TX(mb, GST);
            tma2d(base2,         &mAh, (c + 2) * 64, m0, mb);
            tma2d(base2 + GSA_L, &mAl, (c + 2) * 64, m0, mb);
            tma2d(base2 + GSB_H, &mBh, (c + 2) * 64, yB, mb);
            tma2d(base2 + GSB_L, &mBl, (c + 2) * 64, yB, mb);
        }
    }

#pragma unroll
    for (int mi = 0; mi < 2; ++mi) {
        int gr = m0 + wr * 32 + mi * 16 + (lane >> 2);
#pragma unroll
        for (int nj = 0; nj < 4; ++nj) {
            int gc = n0 + wc * 32 + nj * 8 + (lane & 3) * 2;
            float2 v0, v1;
            v0.x = acc[mi][nj][0]; v0.y = acc[mi][nj][1];
            v1.x = acc[mi][nj][2]; v1.y = acc[mi][nj][3];
            if (bias) {
                float b0 = bias[gc], b1 = bias[gc + 1];
                v0.x += b0; v0.y += b1; v1.x += b0; v1.y += b1;
            }
            *reinterpret_cast<float2*>(C + (size_t)gr * Ncols + gc) = v0;
            *reinterpret_cast<float2*>(C + (size_t)(gr + 8) * Ncols + gc) = v1;
        }
    }
}

// ---------------- SPD log-projection (merged Q+K, blockIdx.y selects) -------
__global__ __launch_bounds__(256)
void lproj_qk(const float* __restrict__ qkv,
              const float* __restrict__ sq_w, const float* __restrict__ sq_b,
              const float* __restrict__ sk_w, const float* __restrict__ sk_b,
              __nv_bfloat16* __restrict__ lqp, __nv_bfloat16* __restrict__ lkp,
              float* __restrict__ lq2, float* __restrict__ lk2)
{
    __shared__ float s_w[RK][HD];
    __shared__ float s_b[RK];
    __shared__ float s_q[128][HD + 1];

    const int sel  = blockIdx.y;        // 0 = Q, 1 = K
    const float* src  = qkv + (size_t)sel * MTOT * DIMC;
    const float* w    = sel ? sk_w : sq_w;
    const float* bias = sel ? sk_b : sq_b;
    __nv_bfloat16* lp = sel ? lkp : lqp;
    float* l2arr      = sel ? lk2 : lq2;

    const int bid  = blockIdx.x;
    const int bh   = bid >> 3;
    const int tile = bid & 7;
    const int b    = bh / NH;
    const int h    = bh - b * NH;
    const int tid  = threadIdx.x;

    ((float*)s_w)[tid]       = w[tid & 511];
    ((float*)s_w)[tid + 256] = w[(tid + 256) & 511];
    if (tid < RK) s_b[tid] = bias[tid];

    const float* base = src + ((size_t)(b * SEQ) + tile * 128) * DIMC + h * HD;
#pragma unroll
    for (int u = 0; u < 8; ++u) {
        int s   = tid + u * 256;
        int row = s >> 4;
        int c4  = (s & 15) << 2;
        float4 v = *reinterpret_cast<const float4*>(base + (size_t)row * DIMC + c4);
        s_q[row][c4 + 0] = v.x; s_q[row][c4 + 1] = v.y;
        s_q[row][c4 + 2] = v.z; s_q[row][c4 + 3] = v.w;
    }
    __syncthreads();

    const int token = tid >> 1;
    const int r0    = (tid & 1) * 4;
    float z0 = s_b[r0 + 0], z1 = s_b[r0 + 1], z2 = s_b[r0 + 2], z3 = s_b[r0 + 3];
#pragma unroll
    for (int d = 0; d < HD; ++d) {
        float q = s_q[token][d];
        z0 = fmaf(q, s_w[r0 + 0][d], z0);
        z1 = fmaf(q, s_w[r0 + 1][d], z1);
        z2 = fmaf(q, s_w[r0 + 2][d], z2);
        z3 = fmaf(q, s_w[r0 + 3][d], z3);
    }
    float zz[4] = {z0, z1, z2, z3};
    float hi4[4], lo4[4];
    float s2 = 0.f;
#pragma unroll
    for (int i = 0; i < 4; ++i) {
        float z = zz[i];
        float sp = (z > 20.f) ? z : log1pf(expf(z));
        float l = 0.125f * logf(sp + 1e-6f + 1e-8f);   // scaled by SCALE
        s2 = fmaf(l, l, s2);
        float h = __bfloat162float(__float2bfloat16(l));
        hi4[i] = h;
        lo4[i] = l - h;
    }
    s2 += __shfl_xor_sync(0xffffffffu, s2, 1);

    const size_t t = (size_t)bh * SEQ + tile * 128 + token;
    uint2 hp, lq;
    hp.x = pack_bf16x2(hi4[0], hi4[1]);
    hp.y = pack_bf16x2(hi4[2], hi4[3]);
    lq.x = pack_bf16x2(lo4[0], lo4[1]);
    lq.y = pack_bf16x2(lo4[2], lo4[3]);
    *reinterpret_cast<uint2*>(lp + t * 16 + r0)     = hp;
    *reinterpret_cast<uint2*>(lp + t * 16 + 8 + r0) = lq;
    if ((tid & 1) == 0) l2arr[t] = s2;
}

// ---------------- SV precompute ---------------------------------------------
__global__ __launch_bounds__(256)
void svsum_kernel()
{
    __shared__ float part[4][HD];
    const int bh = blockIdx.x;
    const int b = bh / NH, h = bh - b * NH;
    const int tid = threadIdx.x;
    const int d = tid & 63, seg = tid >> 6;
    const float* Vp = g_qkv + (size_t)2 * MTOT * DIMC
                    + (size_t)(b * SEQ) * DIMC + h * HD + d;
    float s = 0.f;
    for (int k = seg * 256; k < seg * 256 + 256; ++k)
        s += Vp[(size_t)k * DIMC];
    part[seg][d] = s;
    __syncthreads();
    if (tid < HD)
        g_sv[bh * HD + tid] = part[0][tid] + part[1][tid]
                            + part[2][tid] + part[3][tid];
}

// ---------------- geodesic attention (validated R9) --------------------------
#define AKT 64
#define UP  72
#define LQP 24

__global__ __launch_bounds__(256, 2)
void attn_mma()
{
    __shared__ __align__(16) __nv_bfloat16 s_lq [128][LQP];
    __shared__ __align__(16) __nv_bfloat16 s_lkA[AKT][LQP];
    __shared__ __align__(16) __nv_bfloat16 s_lkB[AKT][LQP];
    __shared__ float s_lk2[AKT];
    __shared__ float s_sv[HD];
    __shared__ float s_linv[128];
    __shared__ __align__(16) __nv_bfloat16 s_v[AKT][UP];

    const int qb = blockIdx.x, bh = blockIdx.y;
    const int b = bh / NH, h = bh - b * NH;
    const int tid = threadIdx.x, lane = tid & 31, w = tid >> 5;
    const int qq = lane >> 2, ii = lane & 3;
    const int rowq = 16 * w + qq;

    {
        int row = tid >> 1, half = tid & 1;
        *reinterpret_cast<uint4*>(&s_lq[row][half * 8]) =
            *reinterpret_cast<const uint4*>(
                g_lqp + ((size_t)bh * SEQ + qb * 128 + row) * 16 + half * 8);
    }
    if (tid < HD) s_sv[tid] = g_sv[bh * HD + tid];
    const float lq2_0 = g_lq2[(size_t)bh * SEQ + qb * 128 + rowq];
    const float lq2_1 = g_lq2[(size_t)bh * SEQ + qb * 128 + rowq + 8];
    __syncthreads();

    uint32_t aF[4];
    ldsm4(aF, smem_u32(&s_lq[16 * w + (lane & 15)][(lane >> 4) * 8]));

    const float* Vp  = g_qkv + (size_t)2 * MTOT * DIMC
                     + (size_t)(b * SEQ) * DIMC + h * HD;
    const __nv_bfloat16* Lkp = g_lkp + (size_t)bh * SEQ * 16;
    const float* Lk2 = g_lk2 + (size_t)bh * SEQ;

    float acc[8][4];
#pragma unroll
    for (int i = 0; i < 8; i++)
#pragma unroll
        for (int j = 0; j < 4; j++) acc[i][j] = 0.f;
    float us0 = 0.f, us1 = 0.f;

    const int rB = ((lane >> 4) & 1) * 8 + (lane & 7);
    const int cB = ((lane >> 3) & 1) * 8;
    const int rL = lane & 15, cL = (lane >> 4) * 8;

    for (int kt = 0; kt < SEQ / AKT; ++kt) {
        const int key0 = kt * AKT;
        __syncthreads();
        if (tid < 64) {
            uint4 hv = *reinterpret_cast<const uint4*>(Lkp + (key0 + tid) * 16);
            *reinterpret_cast<uint4*>(&s_lkA[tid][0]) = hv;
            *reinterpret_cast<uint4*>(&s_lkA[tid][8]) = hv;
        } else if (tid < 128) {
            int r = tid - 64;
            uint4 lv = *reinterpret_cast<const uint4*>(Lkp + (key0 + r) * 16 + 8);
            *reinterpret_cast<uint4*>(&s_lkB[r][0]) = lv;
            *reinterpret_cast<uint4*>(&s_lkB[r][8]) = make_uint4(0, 0, 0, 0);
        } else if (tid < 192) {
            s_lk2[tid - 128] = Lk2[key0 + tid - 128];
        }
#pragma unroll
        for (int u2 = 0; u2 < 4; ++u2) {
            int s = tid + u2 * 256;
            int key = s >> 4, d4 = (s & 15) * 4;
            float4 v = *(const float4*)(Vp + (size_t)(key0 + key) * DIMC + d4);
            uint2 pk;
            pk.x = pack_bf16x2(v.x, v.y);
            pk.y = pack_bf16x2(v.z, v.w);
            *reinterpret_cast<uint2*>(&s_v[key][d4]) = pk;
        }
        __syncthreads();

        uint32_t uA[4][4];
#pragma unroll
        for (int hhalf = 0; hhalf < 2; ++hhalf) {
            float sacc[4][4];
#pragma unroll
            for (int i = 0; i < 4; i++)
#pragma unroll
                for (int j = 0; j < 4; j++) sacc[i][j] = 0.f;
#pragma unroll
            for (int nj = 0; nj < 2; ++nj) {
                int njj = 2 * hhalf + nj;
                uint32_t addr = (njj * 16 + rB) * (LQP * 2) + cB * 2;
                uint32_t r[4];
                ldsm4(r, smem_u32(s_lkA) + addr);
                uint32_t bb0[2] = {r[0], r[1]};
                uint32_t bb1[2] = {r[2], r[3]};
                uint32_t r2[4];
                ldsm4(r2, smem_u32(s_lkB) + addr);
                uint32_t bc0[2] = {r2[0], r2[1]};
                uint32_t bc1[2] = {r2[2], r2[3]};
                mma16816(sacc[2 * nj],     aF, bb0);
                mma16816(sacc[2 * nj],     aF, bc0);
                mma16816(sacc[2 * nj + 1], aF, bb1);
                mma16816(sacc[2 * nj + 1], aF, bc1);
            }
#pragma unroll
            for (int k = 0; k < 4; ++k) {
                int nc = 4 * hhalf + k;
                int col = 8 * nc + 2 * ii;
                float lk0 = s_lk2[col], lk1 = s_lk2[col + 1];
                float d00 = fmaf(-2.f, sacc[k][0], lq2_0 + lk0);
                float d01 = fmaf(-2.f, sacc[k][1], lq2_0 + lk1);
                float d10 = fmaf(-2.f, sacc[k][2], lq2_1 + lk0);
                float d11 = fmaf(-2.f, sacc[k][3], lq2_1 + lk1);
                d00 = fmaxf(d00, 1.5625e-14f);
                d01 = fmaxf(d01, 1.5625e-14f);
                d10 = fmaxf(d10, 1.5625e-14f);
                d11 = fmaxf(d11, 1.5625e-14f);
                float t00 = sqa(d00), t01 = sqa(d01);
                float t10 = sqa(d10), t11 = sqa(d11);
                const float c2 = -0.5f, c3 = 0.16666667f, c4 = -0.041666667f;
                float u00 = t00 * fmaf(t00, fmaf(t00, fmaf(t00, c4, c3), c2), 1.f);
                float u01 = t01 * fmaf(t01, fmaf(t01, fmaf(t01, c4, c3), c2), 1.f);
                float u10 = t10 * fmaf(t10, fmaf(t10, fmaf(t10, c4, c3), c2), 1.f);
                float u11 = t11 * fmaf(t11, fmaf(t11, fmaf(t11, c4, c3), c2), 1.f);
                us0 += u00 + u01;
                us1 += u10 + u11;
                int kc = nc >> 1;
                if ((nc & 1) == 0) {
                    uA[kc][0] = pack_bf16x2(u00, u01);
                    uA[kc][1] = pack_bf16x2(u10, u11);
                } else {
                    uA[kc][2] = pack_bf16x2(u00, u01);
                    uA[kc][3] = pack_bf16x2(u10, u11);
                }
            }
        }

#pragma unroll
        for (int kc = 0; kc < 4; ++kc) {
#pragma unroll
            for (int vc = 0; vc < 4; ++vc) {
                uint32_t r[4];
                ldsm4t(r, smem_u32(&s_v[16 * kc + rL][16 * vc + cL]));
                mma16816(acc[2 * vc],     uA[kc], r);
                mma16816(acc[2 * vc + 1], uA[kc], r + 2);
            }
        }
    }

    us0 += __shfl_xor_sync(0xffffffffu, us0, 1);
    us0 += __shfl_xor_sync(0xffffffffu, us0, 2);
    us1 += __shfl_xor_sync(0xffffffffu, us1, 1);
    us1 += __shfl_xor_sync(0xffffffffu, us1, 2);
    if (ii == 0) {
        s_linv[rowq]     = 1.f / (1024.f - us0);
        s_linv[rowq + 8] = 1.f / (1024.f - us1);
    }
    __syncthreads();

    const float ilo = s_linv[rowq], ihi = s_linv[rowq + 8];
    const size_t rowb = (size_t)(b * SEQ + qb * 128) * DIMC + h * HD;
#pragma unroll
    for (int nc = 0; nc < 8; ++nc) {
        int c = 8 * nc + ii * 2;
        float sv0 = s_sv[c], sv1 = s_sv[c + 1];
        float o00 = (sv0 - acc[nc][0]) * ilo;
        float o01 = (sv1 - acc[nc][1]) * ilo;
        float o10 = (sv0 - acc[nc][2]) * ihi;
        float o11 = (sv1 - acc[nc][3]) * ihi;
        float h00 = __bfloat162float(__float2bfloat16(o00));
        float h01 = __bfloat162float(__float2bfloat16(o01));
        float h10 = __bfloat162float(__float2bfloat16(o10));
        float h11 = __bfloat162float(__float2bfloat16(o11));
        size_t a0 = rowb + (size_t)rowq * DIMC + c;
        size_t a1 = rowb + (size_t)(rowq + 8) * DIMC + c;
        *reinterpret_cast<uint32_t*>(g_ch + a0) = pack_bf16x2(h00, h01);
        *reinterpret_cast<uint32_t*>(g_cl + a0) = pack_bf16x2(o00 - h00, o01 - h01);
        *reinterpret_cast<uint32_t*>(g_ch + a1) = pack_bf16x2(h10, h11);
        *reinterpret_cast<uint32_t*>(g_cl + a1) = pack_bf16x2(o10 - h10, o11 - h11);
    }
}

// ---------------- KL term (vectorized deterministic reduction) --------------
__global__ __launch_bounds__(256)
void kl_partial(const float* __restrict__ m0, const float* __restrict__ l0,
                const float* __restrict__ m1, const float* __restrict__ l1,
                const float* __restrict__ m2, const float* __restrict__ l2,
                const float* __restrict__ m3, const float* __restrict__ l3)
{
    const int PER4 = PER / 4;
    const int TOT4 = 4 * PER4;
    const float L2E2 = 2.0f * 1.4426950408889634f;
    float s = 0.f;
    for (int i4 = blockIdx.x * blockDim.x + threadIdx.x; i4 < TOT4;
         i4 += gridDim.x * blockDim.x) {
        int p   = i4 / PER4;
        int off = i4 - p * PER4;
        const float* mp = (p == 0) ? m0 : (p == 1) ? m1 : (p == 2) ? m2 : m3;
        const float* lp = (p == 0) ? l0 : (p == 1) ? l1 : (p == 2) ? l2 : l3;
        float4 mu = reinterpret_cast<const float4*>(mp)[off];
        float4 ls = reinterpret_cast<const float4*>(lp)[off];
        s += 0.5f * (ex2a(L2E2 * ls.x) + mu.x * mu.x - 1.f - 2.f * ls.x);
        s += 0.5f * (ex2a(L2E2 * ls.y) + mu.y * mu.y - 1.f - 2.f * ls.y);
        s += 0.5f * (ex2a(L2E2 * ls.z) + mu.z * mu.z - 1.f - 2.f * ls.z);
        s += 0.5f * (ex2a(L2E2 * ls.w) + mu.w * mu.w - 1.f - 2.f * ls.w);
    }
    __shared__ float red[256];
    red[threadIdx.x] = s;
    __syncthreads();
    for (int w = 128; w > 0; w >>= 1) {
        if (threadIdx.x < w) red[threadIdx.x] += red[threadIdx.x + w];
        __syncthreads();
    }
    if (threadIdx.x == 0) g_klpart[blockIdx.x] = red[0];
}

__global__ void kl_final(float* __restrict__ dst)
{
    __shared__ float red[256];
    red[threadIdx.x] = g_klpart[threadIdx.x];
    __syncthreads();
    for (int w = 128; w > 0; w >>= 1) {
        if (threadIdx.x < w) red[threadIdx.x] += red[threadIdx.x + w];
        __syncthreads();
    }
    if (threadIdx.x == 0) *dst = red[0];
}

// ---------------- host: tensor map encoding ---------------------------------
typedef CUresult (*PFN_tmEnc)(CUtensorMap*, CUtensorMapDataType, cuuint32_t,
                              void*, const cuuint64_t*, const cuuint64_t*,
                              const cuuint32_t*, const cuuint32_t*,
                              CUtensorMapInterleave, CUtensorMapSwizzle,
                              CUtensorMapL2promotion, CUtensorMapFloatOOBfill);

static void encode_map(PFN_tmEnc fn, CUtensorMap* m, void* ptr,
                       unsigned long long rows, unsigned boxRows)
{
    cuuint64_t dims[2]    = {(cuuint64_t)KDIM, (cuuint64_t)rows};
    cuuint64_t strides[1] = {(cuuint64_t)KDIM * 2};
    cuuint32_t box[2]     = {64u, boxRows};
    cuuint32_t es[2]      = {1u, 1u};
    fn(m, CU_TENSOR_MAP_DATA_TYPE_BFLOAT16, 2, ptr, dims, strides, box, es,
       CU_TENSOR_MAP_INTERLEAVE_NONE, CU_TENSOR_MAP_SWIZZLE_128B,
       CU_TENSOR_MAP_L2_PROMOTION_L2_128B, CU_TENSOR_MAP_FLOAT_OOB_FILL_NONE);
}

// ---------------- launcher -------------------------------------------------
extern "C" void kernel_launch(void* const* d_in, const int* in_sizes, int n_in,
                              void* d_out, int out_size)
{
    const float* x     = (const float*)d_in[0];
    const float* wq_mu = (const float*)d_in[1];
    const float* wq_ls = (const float*)d_in[2];
    const float* wk_mu = (const float*)d_in[3];
    const float* wk_ls = (const float*)d_in[4];
    const float* wv_mu = (const float*)d_in[5];
    const float* wv_ls = (const float*)d_in[6];
    const float* wo_mu = (const float*)d_in[7];
    const float* wo_ls = (const float*)d_in[8];
    const float* wo_b  = (const float*)d_in[9];
    const float* sq_w  = (const float*)d_in[10];
    const float* sq_b  = (const float*)d_in[11];
    const float* sk_w  = (const float*)d_in[12];
    const float* sk_b  = (const float*)d_in[13];
    float* out = (float*)d_out;

    float *qkv_d, *lq2_d, *lk2_d;
    __nv_bfloat16 *lqp_d, *lkp_d;
    __nv_bfloat16 *xh_d, *xl_d, *wh_d, *wl_d, *woh_d, *wol_d, *ch_d, *cl_d;
    cudaGetSymbolAddress((void**)&qkv_d, g_qkv);
    cudaGetSymbolAddress((void**)&lqp_d, g_lqp);
    cudaGetSymbolAddress((void**)&lkp_d, g_lkp);
    cudaGetSymbolAddress((void**)&lq2_d, g_lq2);
    cudaGetSymbolAddress((void**)&lk2_d, g_lk2);
    cudaGetSymbolAddress((void**)&xh_d,  g_xh);
    cudaGetSymbolAddress((void**)&xl_d,  g_xl);
    cudaGetSymbolAddress((void**)&wh_d,  g_wh);
    cudaGetSymbolAddress((void**)&wl_d,  g_wl);
    cudaGetSymbolAddress((void**)&woh_d, g_woh);
    cudaGetSymbolAddress((void**)&wol_d, g_wol);
    cudaGetSymbolAddress((void**)&ch_d,  g_ch);
    cudaGetSymbolAddress((void**)&cl_d,  g_cl);

    static PFN_tmEnc tmEnc = nullptr;
    static cudaStream_t s2 = nullptr;
    static cudaEvent_t evRoot = nullptr, evQKV = nullptr, evSide = nullptr;
    if (!tmEnc) {
        cudaDriverEntryPointQueryResult qr;
        cudaGetDriverEntryPoint("cuTensorMapEncodeTiled", (void**)&tmEnc,
                                cudaEnableDefault, &qr);
        cudaStreamCreateWithFlags(&s2, cudaStreamNonBlocking);
        cudaEventCreateWithFlags(&evRoot, cudaEventDisableTiming);
        cudaEventCreateWithFlags(&evQKV,  cudaEventDisableTiming);
        cudaEventCreateWithFlags(&evSide, cudaEventDisableTiming);
    }
    CUtensorMap mXh, mXl, mWh, mWl, mCh, mCl, mOh, mOl;
    encode_map(tmEnc, &mXh, xh_d,  MTOT,     128);
    encode_map(tmEnc, &mXl, xl_d,  MTOT,     128);
    encode_map(tmEnc, &mWh, wh_d,  3 * DIMC, 64);
    encode_map(tmEnc, &mWl, wl_d,  3 * DIMC, 64);
    encode_map(tmEnc, &mCh, ch_d,  MTOT,     128);
    encode_map(tmEnc, &mCl, cl_d,  MTOT,     128);
    encode_map(tmEnc, &mOh, woh_d, DIMC,     64);
    encode_map(tmEnc, &mOl, wol_d, DIMC,     64);

    cudaFuncSetAttribute(gemm_tma, cudaFuncAttributeMaxDynamicSharedMemorySize,
                         GEMM_DSMEM);

    // fork side stream: KL reduction depends only on inputs
    cudaEventRecord(evRoot, 0);
    cudaStreamWaitEvent(s2, evRoot, 0);
    kl_partial<<<256, 256, 0, s2>>>(wq_mu, wq_ls, wk_mu, wk_ls,
                                    wv_mu, wv_ls, wo_mu, wo_ls);
    if (out_size > MTOT * DIMC) {
        kl_final<<<1, 256, 0, s2>>>(out + (size_t)out_size - 1);
    }

    const int TOTAL4 = MTOT * DIMC / 4 + 4 * (PER / 4);
    split_all<<<TOTAL4 / 256, 256>>>(x, wq_mu, wk_mu, wv_mu, wo_mu);

    gemm_tma<<<dim3(DIMC / 64, MTOT / 128, 3), 256, GEMM_DSMEM>>>(
        mXh, mXl, mWh, mWl, qkv_d, nullptr, DIMC, (size_t)MTOT * DIMC);
    cudaEventRecord(evQKV, 0);

    // svsum on side stream (depends on V plane of QKV gemm)
    cudaStreamWaitEvent(s2, evQKV, 0);
    svsum_kernel<<<BH, 256, 0, s2>>>();
    cudaEventRecord(evSide, s2);

    // merged Q+K log-projection on main stream
    lproj_qk<<<dim3(BH * 8, 2), 256>>>(qkv_d, sq_w, sq_b, sk_w, sk_b,
                                       lqp_d, lkp_d, lq2_d, lk2_d);

    // join side stream before attention (needs g_sv; also joins KL)
    cudaStreamWaitEvent(0, evSide, 0);

    attn_mma<<<dim3(SEQ / 128, BH), 256>>>();

    gemm_tma<<<dim3(DIMC / 64, MTOT / 128, 1), 256, GEMM_DSMEM>>>(
        mCh, mCl, mOh, mOl, out, wo_b, DIMC, 0);
}